// round 4
// baseline (speedup 1.0000x reference)
#include <cuda_runtime.h>
#include <cuda_bf16.h>
#include <math.h>

// ---------------- problem constants ----------------
#define NN_ 200      // nodes
#define UU  64       // rnn units
#define BB  64       // batch
#define TT  12       // T_IN == T_OUT
#define LL  4
#define ROWS (NN_*BB)        // 12800
#define FMAX 264             // layer0: 200+64
#define CHUNK (ROWS*FMAX)    // floats per chebyshev term (gate buffer)
#define RHCH (ROWS*UU)       // floats per rh chebyshev term

typedef unsigned long long u64;

// ---------------- device scratch (static: no runtime allocs) ----------------
__device__ float g_X[3*CHUNK];        // [x0|x1|x2] for gate gconv ([x|h] fused)
__device__ float g_RH[3*RHCH];        // [rh | S@rh | 2S^2rh - rh]
__device__ float g_T [ROWS*UU];       // candidate x-part partial
__device__ float g_U [ROWS*UU];       // update gate u
__device__ float g_H [LL*ROWS*UU];    // hidden states, rows = n*B+b
__device__ float g_PROJ[BB*NN_*NN_];  // previous decoder projection (B, N*N)
__device__ float g_Wg_e[792*128 + 3*384*128];
__device__ float g_Wg_d[792*128 + 3*384*128];
// candidate weights split: x-part (k-major over Fi) and h-part (k-major over 64)
__device__ float g_Wcx_e[3*200*64 + 3*(3*64*64)];
__device__ float g_Wcx_d[3*200*64 + 3*(3*64*64)];
__device__ float g_Wch_e[4*(3*64*64)];
__device__ float g_Wch_d[4*(3*64*64)];

// ---------------- small kernels ----------------
__global__ void zerok(float* p, int n) {
    int i = blockIdx.x * 256 + threadIdx.x;
    if (i < n) p[i] = 0.f;
}

// repack gate weights: src rows (f*3 + k) -> dst rows (k*F + f)
__global__ void wprep(const float* __restrict__ src, float* __restrict__ dst,
                      int F, int out) {
    int idx = blockIdx.x * 256 + threadIdx.x;
    int total = 3 * F * out;
    if (idx >= total) return;
    int c = idx % out;
    int r = idx / out;
    int k = r / F;
    int f = r - k * F;
    dst[idx] = src[(f * 3 + k) * out + c];
}

// repack a feature sub-range [f0, f0+W_) of cand weights into k-major blocks
__global__ void wprep_part(const float* __restrict__ src, float* __restrict__ dst,
                           int f0, int W_, int out) {
    int idx = blockIdx.x * 256 + threadIdx.x;
    int total = 3 * W_ * out;
    if (idx >= total) return;
    int c = idx % out;
    int r = idx / out;
    int k = r / W_;
    int f = r - k * W_;
    dst[idx] = src[((f0 + f) * 3 + k) * out + c];
}

// build concatenated per-node features: dst row (n,b) = [x(Fi) | h(64)]
// xmode: 0 = encoder input (transpose from inputs), 1 = g_PROJ, 2 = zeros,
//        3 = previous layer hidden (rows (n,b), 64)
__global__ void build_cat(float* __restrict__ dst,
                          const float* __restrict__ xsrc, int xmode, int t,
                          const float* __restrict__ st, int Fi) {
    int F = Fi + UU;
    int idx = blockIdx.x * 256 + threadIdx.x;
    int total = ROWS * F;
    if (idx >= total) return;
    int row = idx / F;
    int f = idx - row * F;
    int n = row >> 6, b = row & 63;
    float v;
    if (f < Fi) {
        if (xmode == 0)      v = xsrc[((long)b * TT + t) * 40000 + (long)n * 200 + f];
        else if (xmode == 1) v = xsrc[(long)b * 40000 + (long)n * 200 + f];
        else if (xmode == 2) v = 0.f;
        else                 v = xsrc[row * UU + f];
    } else {
        v = st[row * UU + (f - Fi)];
    }
    dst[(long)row * F + f] = v;
}

// ---------------- FFMA2 SGEMM with fused epilogues ----------------
// C(M,Nn) = A(M,K) @ B(K,Nn), row-major.
// Fblk>0: A is 3 equally spaced chunks (stride ablk), each with row-ld=lda and
//         K-width Fblk (columns 0..Fblk-1 of each chunk used).
// MODE: 0 plain, 1 cheb (2*acc - X0), 2 gates (sigmoid -> RH,U),
//       3 cand (tanh(acc+bias+X0addin) -> GRU update in-place), 4 projection
#define BM 128
#define BN 64
#define BK 8

#define FFMA2(d, a, b) asm("fma.rn.f32x2 %0, %1, %2, %0;" : "+l"(d) : "l"(a), "l"(b))

template<int MODE>
__device__ __forceinline__ void epi(
    float v, int gm, int gn,
    float* Cm, int ldc,
    const float* bias, const float* X0, int ldx0,
    const float* H, float* O1, float* O2, const float* Uin,
    float* out2, int t)
{
    if (MODE == 0) {
        Cm[(long)gm * ldc + gn] = v;
    } else if (MODE == 1) {
        Cm[(long)gm * ldc + gn] = 2.f * v - X0[(long)gm * ldx0 + gn];
    } else if (MODE == 2) {
        float s = 1.f / (1.f + expf(-(v + bias[gn])));
        if (gn < UU) O1[gm * UU + gn] = s * H[gm * UU + gn];   // r*h
        else         O2[gm * UU + gn - UU] = s;                // u
    } else if (MODE == 3) {
        float c = tanhf(v + bias[gn] + X0[(long)gm * ldx0 + gn]);
        float u = Uin[gm * UU + gn];
        O1[gm * UU + gn] = u * H[gm * UU + gn] + (1.f - u) * c;
    } else {  // MODE == 4 projection
        float p = v + bias[gn];
        int b_ = gm & 63, n_ = gm >> 6;
        Cm[((long)b_ * TT + t) * 40000 + (long)n_ * 200 + gn] = p;
        out2[(long)b_ * 40000 + (long)n_ * 200 + gn] = p;
    }
}

template<int MODE>
__global__ __launch_bounds__(256) void gemm_k(
    const float* __restrict__ A, int lda, int Fblk, long ablk,
    const float* __restrict__ Bm, int ldb,
    float* __restrict__ Cm, int ldc,
    int M, int Nn, int K,
    const float* __restrict__ bias,
    const float* __restrict__ X0, int ldx0,
    const float* __restrict__ H,
    float* __restrict__ O1,
    float* __restrict__ O2,
    const float* __restrict__ Uin,
    float* __restrict__ out2, int t)
{
    __shared__ float As[BK][BM];
    __shared__ float Bs[BK][2*BN];   // duplicated pairs: Bs[k][2n]=Bs[k][2n+1]=B[k][n]
    int tid = threadIdx.x;
    int tx = tid & 15, ty = tid >> 4;
    int m0 = blockIdx.y * BM, n0 = blockIdx.x * BN;

    u64 acc[4][4];
#pragma unroll
    for (int i = 0; i < 4; i++)
#pragma unroll
        for (int j = 0; j < 4; j++) acc[i][j] = 0ull;

    int la_m = tid >> 2;             // 0..63
    int la_k = (tid & 3) * 2;        // 0,2,4,6
    int lb_r = tid >> 5;             // 0..7
    int lb_c = (tid & 31) * 2;       // 0..62

    for (int k0 = 0; k0 < K; k0 += BK) {
        const float* Ab = A;
        int krel = k0;
        if (Fblk) {
            int kb = k0 / Fblk;
            Ab = A + (long)kb * ablk;
            krel = k0 - kb * Fblk;
        }
#pragma unroll
        for (int mm = 0; mm < 2; mm++) {
            int m = la_m + mm * 64;
            float x = 0.f, y = 0.f;
            int gm = m0 + m;
            if (gm < M) {
                const float* p = Ab + (long)gm * lda + krel + la_k;
                x = p[0]; y = p[1];
            }
            As[la_k][m] = x;
            As[la_k + 1][m] = y;
        }
        {
            float x = 0.f, y = 0.f;
            int gn = n0 + lb_c;
            if (gn < Nn) {
                const float* p = Bm + (long)(k0 + lb_r) * ldb + gn;
                x = p[0];
                if (gn + 1 < Nn) y = p[1];
            }
            float4 d4 = make_float4(x, x, y, y);
            *reinterpret_cast<float4*>(&Bs[lb_r][2 * lb_c]) = d4;
        }
        __syncthreads();
#pragma unroll
        for (int kk = 0; kk < BK; kk++) {
            ulonglong2 aA = *reinterpret_cast<const ulonglong2*>(&As[kk][ty * 8]);
            ulonglong2 aB = *reinterpret_cast<const ulonglong2*>(&As[kk][ty * 8 + 4]);
            ulonglong2 bA = *reinterpret_cast<const ulonglong2*>(&Bs[kk][tx * 8]);
            ulonglong2 bB = *reinterpret_cast<const ulonglong2*>(&Bs[kk][tx * 8 + 4]);
            u64 ap[4] = {aA.x, aA.y, aB.x, aB.y};   // row pairs (2ip, 2ip+1)
            u64 bp[4] = {bA.x, bA.y, bB.x, bB.y};   // duplicated b values
#pragma unroll
            for (int ip = 0; ip < 4; ip++)
#pragma unroll
                for (int j = 0; j < 4; j++)
                    FFMA2(acc[ip][j], ap[ip], bp[j]);
        }
        __syncthreads();
    }

#pragma unroll
    for (int ip = 0; ip < 4; ip++) {
        int gm0 = m0 + ty * 8 + 2 * ip;
#pragma unroll
        for (int j = 0; j < 4; j++) {
            int gn = n0 + tx * 4 + j;
            if (gn >= Nn) continue;
            float2 v2 = *reinterpret_cast<float2*>(&acc[ip][j]);
            if (gm0 < M)
                epi<MODE>(v2.x, gm0, gn, Cm, ldc, bias, X0, ldx0, H, O1, O2, Uin, out2, t);
            if (gm0 + 1 < M)
                epi<MODE>(v2.y, gm0 + 1, gn, Cm, ldc, bias, X0, ldx0, H, O1, O2, Uin, out2, t);
        }
    }
}

// ---------------- host orchestration ----------------
extern "C" void kernel_launch(void* const* d_in, const int* in_sizes, int n_in,
                              void* d_out, int out_size) {
    (void)in_sizes; (void)n_in; (void)out_size;
    const float* inputs  = (const float*)d_in[0];
    const float* Ssup    = (const float*)d_in[1];
    const float* enc_Wg0 = (const float*)d_in[2];
    const float* enc_bg0 = (const float*)d_in[3];
    const float* enc_Wc0 = (const float*)d_in[4];
    const float* enc_bc0 = (const float*)d_in[5];
    const float* enc_Wg  = (const float*)d_in[6];
    const float* enc_bg  = (const float*)d_in[7];
    const float* enc_Wc  = (const float*)d_in[8];
    const float* enc_bc  = (const float*)d_in[9];
    const float* dec_Wg0 = (const float*)d_in[10];
    const float* dec_bg0 = (const float*)d_in[11];
    const float* dec_Wc0 = (const float*)d_in[12];
    const float* dec_bc0 = (const float*)d_in[13];
    const float* dec_Wg  = (const float*)d_in[14];
    const float* dec_bg  = (const float*)d_in[15];
    const float* dec_Wc  = (const float*)d_in[16];
    const float* dec_bc  = (const float*)d_in[17];
    const float* proj_W  = (const float*)d_in[18];
    const float* proj_b  = (const float*)d_in[19];
    float* out = (float*)d_out;

    float *pX, *pRH, *pT, *pU, *pH, *pPROJ;
    float *pWge, *pWgd, *pWcxe, *pWcxd, *pWche, *pWchd;
    cudaGetSymbolAddress((void**)&pX,    g_X);
    cudaGetSymbolAddress((void**)&pRH,   g_RH);
    cudaGetSymbolAddress((void**)&pT,    g_T);
    cudaGetSymbolAddress((void**)&pU,    g_U);
    cudaGetSymbolAddress((void**)&pH,    g_H);
    cudaGetSymbolAddress((void**)&pPROJ, g_PROJ);
    cudaGetSymbolAddress((void**)&pWge,  g_Wg_e);
    cudaGetSymbolAddress((void**)&pWgd,  g_Wg_d);
    cudaGetSymbolAddress((void**)&pWcxe, g_Wcx_e);
    cudaGetSymbolAddress((void**)&pWcxd, g_Wcx_d);
    cudaGetSymbolAddress((void**)&pWche, g_Wch_e);
    cudaGetSymbolAddress((void**)&pWchd, g_Wch_d);

    // ---- weight repack ----
    wprep<<<(3*264*128)/256, 256>>>(enc_Wg0, pWge, 264, 128);
    wprep<<<(3*264*128)/256, 256>>>(dec_Wg0, pWgd, 264, 128);
    for (int i = 0; i < 3; i++) {
        wprep<<<(3*128*128)/256, 256>>>(enc_Wg + (long)i*384*128,
                                        pWge + 792*128 + (long)i*384*128, 128, 128);
        wprep<<<(3*128*128)/256, 256>>>(dec_Wg + (long)i*384*128,
                                        pWgd + 792*128 + (long)i*384*128, 128, 128);
    }
    // candidate weights: split x-part / h-part, k-major within each
    // layer 0: Fi=200
    wprep_part<<<(3*200*64)/256, 256>>>(enc_Wc0, pWcxe, 0, 200, 64);
    wprep_part<<<(3*200*64)/256, 256>>>(dec_Wc0, pWcxd, 0, 200, 64);
    wprep_part<<<(3*64*64)/256, 256>>>(enc_Wc0, pWche, 200, 64, 64);
    wprep_part<<<(3*64*64)/256, 256>>>(dec_Wc0, pWchd, 200, 64, 64);
    // layers 1..3: Fi=64
    for (int i = 0; i < 3; i++) {
        const float* se = enc_Wc + (long)i*384*64;
        const float* sd = dec_Wc + (long)i*384*64;
        wprep_part<<<(3*64*64)/256, 256>>>(se, pWcxe + 3*200*64 + (long)i*3*64*64, 0, 64, 64);
        wprep_part<<<(3*64*64)/256, 256>>>(sd, pWcxd + 3*200*64 + (long)i*3*64*64, 0, 64, 64);
        wprep_part<<<(3*64*64)/256, 256>>>(se, pWche + (long)(i+1)*3*64*64, 64, 64, 64);
        wprep_part<<<(3*64*64)/256, 256>>>(sd, pWchd + (long)(i+1)*3*64*64, 64, 64, 64);
    }

    // ---- zero initial hidden state ----
    zerok<<<(LL*ROWS*UU)/256, 256>>>(pH, LL*ROWS*UU);

    float* RHD1 = pRH + RHCH;
    float* RHD2 = pRH + 2*RHCH;

    // ---- sequence loop ----
    for (int tg = 0; tg < 2 * TT; tg++) {
        bool enc = (tg < TT);
        int t = enc ? tg : (tg - TT);
        const float* Wgside  = enc ? pWge  : pWgd;
        const float* Wcxside = enc ? pWcxe : pWcxd;
        const float* Wchside = enc ? pWche : pWchd;

        for (int l = 0; l < LL; l++) {
            int Fi = (l == 0) ? 200 : 64;
            int F = Fi + UU;
            int BF = BB * F;
            float* hl = pH + (long)l * ROWS * UU;

            const float* Wg  = (l == 0) ? Wgside : Wgside + 792*128 + (long)(l-1)*384*128;
            const float* Wcx = (l == 0) ? Wcxside : Wcxside + 3*200*64 + (long)(l-1)*3*64*64;
            const float* Wch = Wchside + (long)l*3*64*64;
            const float* bg = enc ? ((l == 0) ? enc_bg0 : enc_bg + (l-1)*128)
                                  : ((l == 0) ? dec_bg0 : dec_bg + (l-1)*128);
            const float* bc = enc ? ((l == 0) ? enc_bc0 : enc_bc + (l-1)*64)
                                  : ((l == 0) ? dec_bc0 : dec_bc + (l-1)*64);

            int xmode;
            const float* xsrc;
            if (l > 0)      { xmode = 3; xsrc = pH + (long)(l-1) * ROWS * UU; }
            else if (enc)   { xmode = 0; xsrc = inputs; }
            else if (t == 0){ xmode = 2; xsrc = pPROJ; }
            else            { xmode = 1; xsrc = pPROJ; }

            // X0 = [x | h]
            build_cat<<<(ROWS*F)/256, 256>>>(pX, xsrc, xmode, t, hl, Fi);
            // X1 = S @ X0
            gemm_k<0><<<dim3(BF/64, 2), 256>>>(Ssup, 200, 0, 0, pX, BF,
                pX + CHUNK, BF, 200, BF, 200,
                nullptr, nullptr, 0, nullptr, nullptr, nullptr, nullptr, nullptr, 0);
            // X2 = 2*S@X1 - X0
            gemm_k<1><<<dim3(BF/64, 2), 256>>>(Ssup, 200, 0, 0, pX + CHUNK, BF,
                pX + 2*CHUNK, BF, 200, BF, 200,
                nullptr, pX, BF, nullptr, nullptr, nullptr, nullptr, nullptr, 0);
            // gates = sigmoid([X0|X1|X2] @ Wg + bg) -> RH(chunk0) = r*h, U = u
            gemm_k<2><<<dim3(2, 100), 256>>>(pX, F, F, (long)CHUNK, Wg, 128,
                nullptr, 0, ROWS, 128, 3*F,
                bg, nullptr, 0, hl, pRH, pU, nullptr, nullptr, 0);
            // RHD1 = S @ RH
            gemm_k<0><<<dim3(64, 2), 256>>>(Ssup, 200, 0, 0, pRH, 4096,
                RHD1, 4096, 200, 4096, 200,
                nullptr, nullptr, 0, nullptr, nullptr, nullptr, nullptr, nullptr, 0);
            // RHD2 = 2*S@RHD1 - RH
            gemm_k<1><<<dim3(64, 2), 256>>>(Ssup, 200, 0, 0, RHD1, 4096,
                RHD2, 4096, 200, 4096, 200,
                nullptr, pRH, 4096, nullptr, nullptr, nullptr, nullptr, nullptr, 0);
            // T = Xcols(0..Fi) of [X0|X1|X2] @ Wcx   (x-part reuse)
            gemm_k<0><<<dim3(1, 100), 256>>>(pX, F, Fi, (long)CHUNK, Wcx, 64,
                pT, 64, ROWS, 64, 3*Fi,
                nullptr, nullptr, 0, nullptr, nullptr, nullptr, nullptr, nullptr, 0);
            // c = tanh(T + [RH|RHD1|RHD2] @ Wch + bc); h = u*h + (1-u)*c (in place)
            gemm_k<3><<<dim3(1, 100), 256>>>(pRH, 64, 64, (long)RHCH, Wch, 64,
                nullptr, 0, ROWS, 64, 192,
                bc, pT, 64, hl, hl, nullptr, pU, nullptr, 0);
        }

        if (!enc) {
            // projection: out[b,t,:] and next decoder input
            gemm_k<4><<<dim3(4, 100), 256>>>(pH + (long)3 * ROWS * UU, UU, 0, 0,
                proj_W, 200, out, 0, ROWS, 200, UU,
                proj_b, nullptr, 0, nullptr, nullptr, nullptr, nullptr, pPROJ, t);
        }
    }
}

// round 6
// speedup vs baseline: 1.7316x; 1.7316x over previous
#include <cuda_runtime.h>
#include <cuda_bf16.h>
#include <math.h>

// ---------------- problem constants ----------------
#define NN_ 200      // nodes
#define UU  64       // rnn units
#define BB  64       // batch
#define TT  12       // T_IN == T_OUT
#define LL  4
#define ROWS (NN_*BB)        // 12800
#define FMAX 264             // layer0: 200+64
#define CHUNK (ROWS*FMAX)    // floats per chebyshev term (gate buffer)
#define RHCH (ROWS*UU)       // floats per rh chebyshev term

// ---------------- device scratch (static: no runtime allocs) ----------------
__device__ float g_X[3*CHUNK];        // [x0|x1|x2] for gate gconv ([x|h] fused)
__device__ float g_RH[3*RHCH];        // [rh | S@rh | 2S^2rh - rh]
__device__ float g_T [ROWS*UU];       // candidate x-part partial
__device__ float g_U [ROWS*UU];       // update gate u
__device__ float g_H [LL*ROWS*UU];    // hidden states, rows = n*B+b
__device__ float g_PROJ[BB*NN_*NN_];  // previous decoder projection (B, N*N)
__device__ float g_Wg_e[792*128 + 3*384*128];
__device__ float g_Wg_d[792*128 + 3*384*128];
// candidate weights split: x-part (k-major over Fi) and h-part (k-major over 64)
__device__ float g_Wcx_e[3*200*64 + 3*(3*64*64)];
__device__ float g_Wcx_d[3*200*64 + 3*(3*64*64)];
__device__ float g_Wch_e[4*(3*64*64)];
__device__ float g_Wch_d[4*(3*64*64)];

// ---------------- small kernels ----------------
__global__ void zerok(float* p, int n) {
    int i = blockIdx.x * 256 + threadIdx.x;
    if (i < n) p[i] = 0.f;
}

// repack gate weights: src rows (f*3 + k) -> dst rows (k*F + f)
__global__ void wprep(const float* __restrict__ src, float* __restrict__ dst,
                      int F, int out) {
    int idx = blockIdx.x * 256 + threadIdx.x;
    int total = 3 * F * out;
    if (idx >= total) return;
    int c = idx % out;
    int r = idx / out;
    int k = r / F;
    int f = r - k * F;
    dst[idx] = src[(f * 3 + k) * out + c];
}

// repack a feature sub-range [f0, f0+W_) of cand weights into k-major blocks
__global__ void wprep_part(const float* __restrict__ src, float* __restrict__ dst,
                           int f0, int W_, int out) {
    int idx = blockIdx.x * 256 + threadIdx.x;
    int total = 3 * W_ * out;
    if (idx >= total) return;
    int c = idx % out;
    int r = idx / out;
    int k = r / W_;
    int f = r - k * W_;
    dst[idx] = src[((f0 + f) * 3 + k) * out + c];
}

// build concatenated per-node features: dst row (n,b) = [x(Fi) | h(64)]
// xmode: 0 = encoder input (transpose from inputs), 1 = g_PROJ, 2 = zeros,
//        3 = previous layer hidden (rows (n,b), 64)
__global__ void build_cat(float* __restrict__ dst,
                          const float* __restrict__ xsrc, int xmode, int t,
                          const float* __restrict__ st, int Fi) {
    int F = Fi + UU;
    int idx = blockIdx.x * 256 + threadIdx.x;
    int total = ROWS * F;
    if (idx >= total) return;
    int row = idx / F;
    int f = idx - row * F;
    int n = row >> 6, b = row & 63;
    float v;
    if (f < Fi) {
        if (xmode == 0)      v = xsrc[((long)b * TT + t) * 40000 + (long)n * 200 + f];
        else if (xmode == 1) v = xsrc[(long)b * 40000 + (long)n * 200 + f];
        else if (xmode == 2) v = 0.f;
        else                 v = xsrc[row * UU + f];
    } else {
        v = st[row * UU + (f - Fi)];
    }
    dst[(long)row * F + f] = v;
}

// ---------------- SGEMM (scalar FFMA, ping-pong smem) with fused epilogues ----
// C(M,Nn) = A(M,K) @ B(K,Nn), row-major.
// Fblk>0: A is 3 equally spaced chunks (stride ablk), each with row-ld=lda and
//         K-width Fblk (columns 0..Fblk-1 of each chunk used).
// MODE: 0 plain, 1 cheb (2*acc - X0), 2 gates (sigmoid -> RH,U),
//       3 cand (tanh(acc+bias+X0addin) -> GRU update in-place), 4 projection
#define BM 128
#define BN 64
#define BK 8

template<int MODE>
__device__ __forceinline__ void epi(
    float v, int gm, int gn,
    float* Cm, int ldc,
    const float* bias, const float* X0, int ldx0,
    const float* H, float* O1, float* O2, const float* Uin,
    float* out2, int t)
{
    if (MODE == 0) {
        Cm[(long)gm * ldc + gn] = v;
    } else if (MODE == 1) {
        Cm[(long)gm * ldc + gn] = 2.f * v - X0[(long)gm * ldx0 + gn];
    } else if (MODE == 2) {
        float s = 1.f / (1.f + expf(-(v + bias[gn])));
        if (gn < UU) O1[gm * UU + gn] = s * H[gm * UU + gn];   // r*h
        else         O2[gm * UU + gn - UU] = s;                // u
    } else if (MODE == 3) {
        float c = tanhf(v + bias[gn] + X0[(long)gm * ldx0 + gn]);
        float u = Uin[gm * UU + gn];
        O1[gm * UU + gn] = u * H[gm * UU + gn] + (1.f - u) * c;
    } else {  // MODE == 4 projection
        float p = v + bias[gn];
        int b_ = gm & 63, n_ = gm >> 6;
        Cm[((long)b_ * TT + t) * 40000 + (long)n_ * 200 + gn] = p;
        out2[(long)b_ * 40000 + (long)n_ * 200 + gn] = p;
    }
}

template<int MODE>
__global__ __launch_bounds__(256) void gemm_k(
    const float* __restrict__ A, int lda, int Fblk, long ablk,
    const float* __restrict__ Bm, int ldb,
    float* __restrict__ Cm, int ldc,
    int M, int Nn, int K,
    const float* __restrict__ bias,
    const float* __restrict__ X0, int ldx0,
    const float* __restrict__ H,
    float* __restrict__ O1,
    float* __restrict__ O2,
    const float* __restrict__ Uin,
    float* __restrict__ out2, int t)
{
    __shared__ float As[2][BK][BM];
    __shared__ float Bs[2][BK][BN];
    int tid = threadIdx.x;
    int tx = tid & 15, ty = tid >> 4;
    int m0 = blockIdx.y * BM, n0 = blockIdx.x * BN;

    float acc[8][4];
#pragma unroll
    for (int i = 0; i < 8; i++)
#pragma unroll
        for (int j = 0; j < 4; j++) acc[i][j] = 0.f;

    int la_m = tid >> 2;             // 0..63
    int la_k = (tid & 3) * 2;        // 0,2,4,6
    int lb_r = tid >> 5;             // 0..7
    int lb_c = (tid & 31) * 2;       // 0..62

    int nk = (K + BK - 1) / BK;

    // fetch one k-tile into registers
    float ra[2][2], rb[2];
    auto fetch = [&](int k0) {
        const float* Ab = A;
        int krel = k0;
        if (Fblk) {
            int kb = k0 / Fblk;
            Ab = A + (long)kb * ablk;
            krel = k0 - kb * Fblk;
        }
#pragma unroll
        for (int mm = 0; mm < 2; mm++) {
            int gm = m0 + la_m + mm * 64;
            float x = 0.f, y = 0.f;
            if (gm < M && krel + la_k < K) {
                const float* p = Ab + (long)gm * lda + krel + la_k;
                x = p[0]; y = p[1];
            }
            ra[mm][0] = x; ra[mm][1] = y;
        }
        {
            float x = 0.f, y = 0.f;
            int gn = n0 + lb_c;
            int gk = k0 + lb_r;
            if (gn < Nn && gk < K) {
                const float* p = Bm + (long)gk * ldb + gn;
                x = p[0]; y = p[1];
            }
            rb[0] = x; rb[1] = y;
        }
    };
    auto store_smem = [&](int buf) {
#pragma unroll
        for (int mm = 0; mm < 2; mm++) {
            As[buf][la_k][la_m + mm * 64] = ra[mm][0];
            As[buf][la_k + 1][la_m + mm * 64] = ra[mm][1];
        }
        Bs[buf][lb_r][lb_c] = rb[0];
        Bs[buf][lb_r][lb_c + 1] = rb[1];
    };

    fetch(0);
    store_smem(0);
    __syncthreads();

    for (int kt = 0; kt < nk; kt++) {
        int cur = kt & 1;
        if (kt + 1 < nk) fetch((kt + 1) * BK);
#pragma unroll
        for (int kk = 0; kk < BK; kk++) {
            float a[8], bb[4];
#pragma unroll
            for (int i = 0; i < 8; i++) a[i] = As[cur][kk][ty * 8 + i];
#pragma unroll
            for (int j = 0; j < 4; j++) bb[j] = Bs[cur][kk][tx * 4 + j];
#pragma unroll
            for (int i = 0; i < 8; i++)
#pragma unroll
                for (int j = 0; j < 4; j++) acc[i][j] += a[i] * bb[j];
        }
        if (kt + 1 < nk) {
            store_smem(cur ^ 1);
            __syncthreads();
        }
    }

#pragma unroll
    for (int i = 0; i < 8; i++) {
        int gm = m0 + ty * 8 + i;
        if (gm >= M) continue;
#pragma unroll
        for (int j = 0; j < 4; j++) {
            int gn = n0 + tx * 4 + j;
            if (gn >= Nn) continue;
            epi<MODE>(acc[i][j], gm, gn, Cm, ldc, bias, X0, ldx0, H, O1, O2, Uin, out2, t);
        }
    }
}

// ---------------- host orchestration ----------------
extern "C" void kernel_launch(void* const* d_in, const int* in_sizes, int n_in,
                              void* d_out, int out_size) {
    (void)in_sizes; (void)n_in; (void)out_size;
    const float* inputs  = (const float*)d_in[0];
    const float* Ssup    = (const float*)d_in[1];
    const float* enc_Wg0 = (const float*)d_in[2];
    const float* enc_bg0 = (const float*)d_in[3];
    const float* enc_Wc0 = (const float*)d_in[4];
    const float* enc_bc0 = (const float*)d_in[5];
    const float* enc_Wg  = (const float*)d_in[6];
    const float* enc_bg  = (const float*)d_in[7];
    const float* enc_Wc  = (const float*)d_in[8];
    const float* enc_bc  = (const float*)d_in[9];
    const float* dec_Wg0 = (const float*)d_in[10];
    const float* dec_bg0 = (const float*)d_in[11];
    const float* dec_Wc0 = (const float*)d_in[12];
    const float* dec_bc0 = (const float*)d_in[13];
    const float* dec_Wg  = (const float*)d_in[14];
    const float* dec_bg  = (const float*)d_in[15];
    const float* dec_Wc  = (const float*)d_in[16];
    const float* dec_bc  = (const float*)d_in[17];
    const float* proj_W  = (const float*)d_in[18];
    const float* proj_b  = (const float*)d_in[19];
    float* out = (float*)d_out;

    float *pX, *pRH, *pT, *pU, *pH, *pPROJ;
    float *pWge, *pWgd, *pWcxe, *pWcxd, *pWche, *pWchd;
    cudaGetSymbolAddress((void**)&pX,    g_X);
    cudaGetSymbolAddress((void**)&pRH,   g_RH);
    cudaGetSymbolAddress((void**)&pT,    g_T);
    cudaGetSymbolAddress((void**)&pU,    g_U);
    cudaGetSymbolAddress((void**)&pH,    g_H);
    cudaGetSymbolAddress((void**)&pPROJ, g_PROJ);
    cudaGetSymbolAddress((void**)&pWge,  g_Wg_e);
    cudaGetSymbolAddress((void**)&pWgd,  g_Wg_d);
    cudaGetSymbolAddress((void**)&pWcxe, g_Wcx_e);
    cudaGetSymbolAddress((void**)&pWcxd, g_Wcx_d);
    cudaGetSymbolAddress((void**)&pWche, g_Wch_e);
    cudaGetSymbolAddress((void**)&pWchd, g_Wch_d);

    // ---- weight repack ----
    wprep<<<(3*264*128)/256, 256>>>(enc_Wg0, pWge, 264, 128);
    wprep<<<(3*264*128)/256, 256>>>(dec_Wg0, pWgd, 264, 128);
    for (int i = 0; i < 3; i++) {
        wprep<<<(3*128*128)/256, 256>>>(enc_Wg + (long)i*384*128,
                                        pWge + 792*128 + (long)i*384*128, 128, 128);
        wprep<<<(3*128*128)/256, 256>>>(dec_Wg + (long)i*384*128,
                                        pWgd + 792*128 + (long)i*384*128, 128, 128);
    }
    // candidate weights: split x-part / h-part, k-major within each
    wprep_part<<<(3*200*64)/256, 256>>>(enc_Wc0, pWcxe, 0, 200, 64);
    wprep_part<<<(3*200*64)/256, 256>>>(dec_Wc0, pWcxd, 0, 200, 64);
    wprep_part<<<(3*64*64)/256, 256>>>(enc_Wc0, pWche, 200, 64, 64);
    wprep_part<<<(3*64*64)/256, 256>>>(dec_Wc0, pWchd, 200, 64, 64);
    for (int i = 0; i < 3; i++) {
        const float* se = enc_Wc + (long)i*384*64;
        const float* sd = dec_Wc + (long)i*384*64;
        wprep_part<<<(3*64*64)/256, 256>>>(se, pWcxe + 3*200*64 + (long)i*3*64*64, 0, 64, 64);
        wprep_part<<<(3*64*64)/256, 256>>>(sd, pWcxd + 3*200*64 + (long)i*3*64*64, 0, 64, 64);
        wprep_part<<<(3*64*64)/256, 256>>>(se, pWche + (long)(i+1)*3*64*64, 64, 64, 64);
        wprep_part<<<(3*64*64)/256, 256>>>(sd, pWchd + (long)(i+1)*3*64*64, 64, 64, 64);
    }

    // ---- zero initial hidden state ----
    zerok<<<(LL*ROWS*UU)/256, 256>>>(pH, LL*ROWS*UU);

    float* RHD1 = pRH + RHCH;
    float* RHD2 = pRH + 2*RHCH;

    // ---- sequence loop ----
    for (int tg = 0; tg < 2 * TT; tg++) {
        bool enc = (tg < TT);
        int t = enc ? tg : (tg - TT);
        const float* Wgside  = enc ? pWge  : pWgd;
        const float* Wcxside = enc ? pWcxe : pWcxd;
        const float* Wchside = enc ? pWche : pWchd;

        for (int l = 0; l < LL; l++) {
            int Fi = (l == 0) ? 200 : 64;
            int F = Fi + UU;
            int BF = BB * F;
            float* hl = pH + (long)l * ROWS * UU;

            const float* Wg  = (l == 0) ? Wgside : Wgside + 792*128 + (long)(l-1)*384*128;
            const float* Wcx = (l == 0) ? Wcxside : Wcxside + 3*200*64 + (long)(l-1)*3*64*64;
            const float* Wch = Wchside + (long)l*3*64*64;
            const float* bg = enc ? ((l == 0) ? enc_bg0 : enc_bg + (l-1)*128)
                                  : ((l == 0) ? dec_bg0 : dec_bg + (l-1)*128);
            const float* bc = enc ? ((l == 0) ? enc_bc0 : enc_bc + (l-1)*64)
                                  : ((l == 0) ? dec_bc0 : dec_bc + (l-1)*64);

            int xmode;
            const float* xsrc;
            if (l > 0)      { xmode = 3; xsrc = pH + (long)(l-1) * ROWS * UU; }
            else if (enc)   { xmode = 0; xsrc = inputs; }
            else if (t == 0){ xmode = 2; xsrc = pPROJ; }
            else            { xmode = 1; xsrc = pPROJ; }

            // X0 = [x | h]
            build_cat<<<(ROWS*F)/256, 256>>>(pX, xsrc, xmode, t, hl, Fi);
            // X1 = S @ X0
            gemm_k<0><<<dim3(BF/64, 2), 256>>>(Ssup, 200, 0, 0, pX, BF,
                pX + CHUNK, BF, 200, BF, 200,
                nullptr, nullptr, 0, nullptr, nullptr, nullptr, nullptr, nullptr, 0);
            // X2 = 2*S@X1 - X0
            gemm_k<1><<<dim3(BF/64, 2), 256>>>(Ssup, 200, 0, 0, pX + CHUNK, BF,
                pX + 2*CHUNK, BF, 200, BF, 200,
                nullptr, pX, BF, nullptr, nullptr, nullptr, nullptr, nullptr, 0);
            // gates = sigmoid([X0|X1|X2] @ Wg + bg) -> RH(chunk0) = r*h, U = u
            gemm_k<2><<<dim3(2, 100), 256>>>(pX, F, F, (long)CHUNK, Wg, 128,
                nullptr, 0, ROWS, 128, 3*F,
                bg, nullptr, 0, hl, pRH, pU, nullptr, nullptr, 0);
            // RHD1 = S @ RH
            gemm_k<0><<<dim3(64, 2), 256>>>(Ssup, 200, 0, 0, pRH, 4096,
                RHD1, 4096, 200, 4096, 200,
                nullptr, nullptr, 0, nullptr, nullptr, nullptr, nullptr, nullptr, 0);
            // RHD2 = 2*S@RHD1 - RH
            gemm_k<1><<<dim3(64, 2), 256>>>(Ssup, 200, 0, 0, RHD1, 4096,
                RHD2, 4096, 200, 4096, 200,
                nullptr, pRH, 4096, nullptr, nullptr, nullptr, nullptr, nullptr, 0);
            // T = Xcols(0..Fi) of [X0|X1|X2] @ Wcx   (x-part reuse)
            gemm_k<0><<<dim3(1, 100), 256>>>(pX, F, Fi, (long)CHUNK, Wcx, 64,
                pT, 64, ROWS, 64, 3*Fi,
                nullptr, nullptr, 0, nullptr, nullptr, nullptr, nullptr, nullptr, 0);
            // c = tanh(T + [RH|RHD1|RHD2] @ Wch + bc); h = u*h + (1-u)*c (in place)
            gemm_k<3><<<dim3(1, 100), 256>>>(pRH, 64, 64, (long)RHCH, Wch, 64,
                nullptr, 0, ROWS, 64, 192,
                bc, pT, 64, hl, hl, nullptr, pU, nullptr, 0);
        }

        if (!enc) {
            // projection: out[b,t,:] and next decoder input
            gemm_k<4><<<dim3(4, 100), 256>>>(pH + (long)3 * ROWS * UU, UU, 0, 0,
                proj_W, 200, out, 0, ROWS, 200, UU,
                proj_b, nullptr, 0, nullptr, nullptr, nullptr, nullptr, pPROJ, t);
        }
    }
}

// round 7
// speedup vs baseline: 1.7325x; 1.0005x over previous
#include <cuda_runtime.h>
#include <cuda_bf16.h>
#include <math.h>

// ---------------- problem constants ----------------
#define NN_ 200      // nodes
#define UU  64       // rnn units
#define BB  64       // batch
#define TT  12       // T_IN == T_OUT
#define LL  4
#define ROWS (NN_*BB)        // 12800
#define FMAX 264             // layer0: 200+64
#define CHUNK (ROWS*FMAX)    // floats per chebyshev term (gate buffer)
#define RHCH (ROWS*UU)       // floats per rh chebyshev term

// ---------------- device scratch (static: no runtime allocs) ----------------
__device__ float g_X[3*CHUNK];        // [x0|x1|x2] for gate gconv ([x|h] fused)
__device__ float g_RH[3*RHCH];        // [rh | S@rh | 2S^2rh - rh]
__device__ float g_T [ROWS*UU];       // candidate x-part partial
__device__ float g_U [ROWS*UU];       // update gate u
__device__ float g_H [LL*ROWS*UU];    // hidden states, rows = n*B+b
__device__ float g_PROJ[BB*NN_*NN_];  // previous decoder projection (B, N*N)
__device__ float g_Wg_e[792*128 + 3*384*128];
__device__ float g_Wg_d[792*128 + 3*384*128];
// candidate weights split: x-part (k-major over Fi) and h-part (k-major over 64)
__device__ float g_Wcx_e[3*200*64 + 3*(3*64*64)];
__device__ float g_Wcx_d[3*200*64 + 3*(3*64*64)];
__device__ float g_Wch_e[4*(3*64*64)];
__device__ float g_Wch_d[4*(3*64*64)];

// ---------------- small kernels ----------------
__global__ void zerok(float* p, int n) {
    int i = blockIdx.x * 256 + threadIdx.x;
    if (i < n) p[i] = 0.f;
}

// repack gate weights: src rows (f*3 + k) -> dst rows (k*F + f)
__global__ void wprep(const float* __restrict__ src, float* __restrict__ dst,
                      int F, int out) {
    int idx = blockIdx.x * 256 + threadIdx.x;
    int total = 3 * F * out;
    if (idx >= total) return;
    int c = idx % out;
    int r = idx / out;
    int k = r / F;
    int f = r - k * F;
    dst[idx] = src[(f * 3 + k) * out + c];
}

// repack a feature sub-range [f0, f0+W_) of cand weights into k-major blocks
__global__ void wprep_part(const float* __restrict__ src, float* __restrict__ dst,
                           int f0, int W_, int out) {
    int idx = blockIdx.x * 256 + threadIdx.x;
    int total = 3 * W_ * out;
    if (idx >= total) return;
    int c = idx % out;
    int r = idx / out;
    int k = r / W_;
    int f = r - k * W_;
    dst[idx] = src[((f0 + f) * 3 + k) * out + c];
}

// build concatenated per-node features: dst row (n,b) = [x(Fi) | h(64)]
// xmode: 0 = encoder input (transpose from inputs), 1 = g_PROJ, 2 = zeros,
//        3 = previous layer hidden (rows (n,b), 64)
__global__ void build_cat(float* __restrict__ dst,
                          const float* __restrict__ xsrc, int xmode, int t,
                          const float* __restrict__ st, int Fi) {
    int F = Fi + UU;
    int idx = blockIdx.x * 256 + threadIdx.x;
    int total = ROWS * F;
    if (idx >= total) return;
    int row = idx / F;
    int f = idx - row * F;
    int n = row >> 6, b = row & 63;
    float v;
    if (f < Fi) {
        if (xmode == 0)      v = xsrc[((long)b * TT + t) * 40000 + (long)n * 200 + f];
        else if (xmode == 1) v = xsrc[(long)b * 40000 + (long)n * 200 + f];
        else if (xmode == 2) v = 0.f;
        else                 v = xsrc[row * UU + f];
    } else {
        v = st[row * UU + (f - Fi)];
    }
    dst[(long)row * F + f] = v;
}

// ---------------- SGEMM (scalar FFMA, ping-pong smem) with fused epilogues ----
// C(M,Nn) = A(M,K) @ B(K,Nn), row-major.
// Fblk>0: A is 3 equally spaced chunks (stride ablk), each with row-ld=lda and
//         K-width Fblk (columns 0..Fblk-1 of each chunk used).
// MODE: 0 plain, 1 cheb (2*acc - X0), 2 gates (sigmoid -> RH,U),
//       3 cand (tanh(acc+bias+X0addin) -> GRU update in-place), 4 projection
#define BM 128
#define BN 64
#define BK 8

template<int MODE>
__device__ __forceinline__ void epi(
    float v, int gm, int gn,
    float* Cm, int ldc,
    const float* bias, const float* X0, int ldx0,
    const float* H, float* O1, float* O2, const float* Uin,
    float* out2, int t)
{
    if (MODE == 0) {
        Cm[(long)gm * ldc + gn] = v;
    } else if (MODE == 1) {
        Cm[(long)gm * ldc + gn] = 2.f * v - X0[(long)gm * ldx0 + gn];
    } else if (MODE == 2) {
        float s = 1.f / (1.f + expf(-(v + bias[gn])));
        if (gn < UU) O1[gm * UU + gn] = s * H[gm * UU + gn];   // r*h
        else         O2[gm * UU + gn - UU] = s;                // u
    } else if (MODE == 3) {
        float c = tanhf(v + bias[gn] + X0[(long)gm * ldx0 + gn]);
        float u = Uin[gm * UU + gn];
        O1[gm * UU + gn] = u * H[gm * UU + gn] + (1.f - u) * c;
    } else {  // MODE == 4 projection
        float p = v + bias[gn];
        int b_ = gm & 63, n_ = gm >> 6;
        Cm[((long)b_ * TT + t) * 40000 + (long)n_ * 200 + gn] = p;
        out2[(long)b_ * 40000 + (long)n_ * 200 + gn] = p;
    }
}

template<int MODE>
__global__ __launch_bounds__(256) void gemm_k(
    const float* __restrict__ A, int lda, int Fblk, long ablk,
    const float* __restrict__ Bm, int ldb,
    float* __restrict__ Cm, int ldc,
    int M, int Nn, int K,
    const float* __restrict__ bias,
    const float* __restrict__ X0, int ldx0,
    const float* __restrict__ H,
    float* __restrict__ O1,
    float* __restrict__ O2,
    const float* __restrict__ Uin,
    float* __restrict__ out2, int t)
{
    __shared__ float As[2][BK][BM];
    __shared__ float Bs[2][BK][BN];
    int tid = threadIdx.x;
    int tx = tid & 15, ty = tid >> 4;
    int m0 = blockIdx.y * BM, n0 = blockIdx.x * BN;

    float acc[8][4];
#pragma unroll
    for (int i = 0; i < 8; i++)
#pragma unroll
        for (int j = 0; j < 4; j++) acc[i][j] = 0.f;

    int la_m = tid >> 2;             // 0..63
    int la_k = (tid & 3) * 2;        // 0,2,4,6
    int lb_r = tid >> 5;             // 0..7
    int lb_c = (tid & 31) * 2;       // 0..62

    int nk = (K + BK - 1) / BK;

    // fetch one k-tile into registers
    float ra[2][2], rb[2];
    auto fetch = [&](int k0) {
        const float* Ab = A;
        int krel = k0;
        if (Fblk) {
            int kb = k0 / Fblk;
            Ab = A + (long)kb * ablk;
            krel = k0 - kb * Fblk;
        }
#pragma unroll
        for (int mm = 0; mm < 2; mm++) {
            int gm = m0 + la_m + mm * 64;
            float x = 0.f, y = 0.f;
            if (gm < M && krel + la_k < K) {
                const float* p = Ab + (long)gm * lda + krel + la_k;
                x = p[0]; y = p[1];
            }
            ra[mm][0] = x; ra[mm][1] = y;
        }
        {
            float x = 0.f, y = 0.f;
            int gn = n0 + lb_c;
            int gk = k0 + lb_r;
            if (gn < Nn && gk < K) {
                const float* p = Bm + (long)gk * ldb + gn;
                x = p[0]; y = p[1];
            }
            rb[0] = x; rb[1] = y;
        }
    };
    auto store_smem = [&](int buf) {
#pragma unroll
        for (int mm = 0; mm < 2; mm++) {
            As[buf][la_k][la_m + mm * 64] = ra[mm][0];
            As[buf][la_k + 1][la_m + mm * 64] = ra[mm][1];
        }
        Bs[buf][lb_r][lb_c] = rb[0];
        Bs[buf][lb_r][lb_c + 1] = rb[1];
    };

    fetch(0);
    store_smem(0);
    __syncthreads();

    for (int kt = 0; kt < nk; kt++) {
        int cur = kt & 1;
        if (kt + 1 < nk) fetch((kt + 1) * BK);
#pragma unroll
        for (int kk = 0; kk < BK; kk++) {
            float a[8], bb[4];
#pragma unroll
            for (int i = 0; i < 8; i++) a[i] = As[cur][kk][ty * 8 + i];
#pragma unroll
            for (int j = 0; j < 4; j++) bb[j] = Bs[cur][kk][tx * 4 + j];
#pragma unroll
            for (int i = 0; i < 8; i++)
#pragma unroll
                for (int j = 0; j < 4; j++) acc[i][j] += a[i] * bb[j];
        }
        if (kt + 1 < nk) {
            store_smem(cur ^ 1);
            __syncthreads();
        }
    }

#pragma unroll
    for (int i = 0; i < 8; i++) {
        int gm = m0 + ty * 8 + i;
        if (gm >= M) continue;
#pragma unroll
        for (int j = 0; j < 4; j++) {
            int gn = n0 + tx * 4 + j;
            if (gn >= Nn) continue;
            epi<MODE>(acc[i][j], gm, gn, Cm, ldc, bias, X0, ldx0, H, O1, O2, Uin, out2, t);
        }
    }
}

// ---------------- host orchestration ----------------
extern "C" void kernel_launch(void* const* d_in, const int* in_sizes, int n_in,
                              void* d_out, int out_size) {
    (void)in_sizes; (void)n_in; (void)out_size;
    const float* inputs  = (const float*)d_in[0];
    const float* Ssup    = (const float*)d_in[1];
    const float* enc_Wg0 = (const float*)d_in[2];
    const float* enc_bg0 = (const float*)d_in[3];
    const float* enc_Wc0 = (const float*)d_in[4];
    const float* enc_bc0 = (const float*)d_in[5];
    const float* enc_Wg  = (const float*)d_in[6];
    const float* enc_bg  = (const float*)d_in[7];
    const float* enc_Wc  = (const float*)d_in[8];
    const float* enc_bc  = (const float*)d_in[9];
    const float* dec_Wg0 = (const float*)d_in[10];
    const float* dec_bg0 = (const float*)d_in[11];
    const float* dec_Wc0 = (const float*)d_in[12];
    const float* dec_bc0 = (const float*)d_in[13];
    const float* dec_Wg  = (const float*)d_in[14];
    const float* dec_bg  = (const float*)d_in[15];
    const float* dec_Wc  = (const float*)d_in[16];
    const float* dec_bc  = (const float*)d_in[17];
    const float* proj_W  = (const float*)d_in[18];
    const float* proj_b  = (const float*)d_in[19];
    float* out = (float*)d_out;

    float *pX, *pRH, *pT, *pU, *pH, *pPROJ;
    float *pWge, *pWgd, *pWcxe, *pWcxd, *pWche, *pWchd;
    cudaGetSymbolAddress((void**)&pX,    g_X);
    cudaGetSymbolAddress((void**)&pRH,   g_RH);
    cudaGetSymbolAddress((void**)&pT,    g_T);
    cudaGetSymbolAddress((void**)&pU,    g_U);
    cudaGetSymbolAddress((void**)&pH,    g_H);
    cudaGetSymbolAddress((void**)&pPROJ, g_PROJ);
    cudaGetSymbolAddress((void**)&pWge,  g_Wg_e);
    cudaGetSymbolAddress((void**)&pWgd,  g_Wg_d);
    cudaGetSymbolAddress((void**)&pWcxe, g_Wcx_e);
    cudaGetSymbolAddress((void**)&pWcxd, g_Wcx_d);
    cudaGetSymbolAddress((void**)&pWche, g_Wch_e);
    cudaGetSymbolAddress((void**)&pWchd, g_Wch_d);

    // ---- weight repack ----
    wprep<<<(3*264*128)/256, 256>>>(enc_Wg0, pWge, 264, 128);
    wprep<<<(3*264*128)/256, 256>>>(dec_Wg0, pWgd, 264, 128);
    for (int i = 0; i < 3; i++) {
        wprep<<<(3*128*128)/256, 256>>>(enc_Wg + (long)i*384*128,
                                        pWge + 792*128 + (long)i*384*128, 128, 128);
        wprep<<<(3*128*128)/256, 256>>>(dec_Wg + (long)i*384*128,
                                        pWgd + 792*128 + (long)i*384*128, 128, 128);
    }
    // candidate weights: split x-part / h-part, k-major within each
    wprep_part<<<(3*200*64)/256, 256>>>(enc_Wc0, pWcxe, 0, 200, 64);
    wprep_part<<<(3*200*64)/256, 256>>>(dec_Wc0, pWcxd, 0, 200, 64);
    wprep_part<<<(3*64*64)/256, 256>>>(enc_Wc0, pWche, 200, 64, 64);
    wprep_part<<<(3*64*64)/256, 256>>>(dec_Wc0, pWchd, 200, 64, 64);
    for (int i = 0; i < 3; i++) {
        const float* se = enc_Wc + (long)i*384*64;
        const float* sd = dec_Wc + (long)i*384*64;
        wprep_part<<<(3*64*64)/256, 256>>>(se, pWcxe + 3*200*64 + (long)i*3*64*64, 0, 64, 64);
        wprep_part<<<(3*64*64)/256, 256>>>(sd, pWcxd + 3*200*64 + (long)i*3*64*64, 0, 64, 64);
        wprep_part<<<(3*64*64)/256, 256>>>(se, pWche + (long)(i+1)*3*64*64, 64, 64, 64);
        wprep_part<<<(3*64*64)/256, 256>>>(sd, pWchd + (long)(i+1)*3*64*64, 64, 64, 64);
    }

    // ---- zero initial hidden state ----
    zerok<<<(LL*ROWS*UU)/256, 256>>>(pH, LL*ROWS*UU);

    float* RHD1 = pRH + RHCH;
    float* RHD2 = pRH + 2*RHCH;

    // ---- sequence loop ----
    for (int tg = 0; tg < 2 * TT; tg++) {
        bool enc = (tg < TT);
        int t = enc ? tg : (tg - TT);
        const float* Wgside  = enc ? pWge  : pWgd;
        const float* Wcxside = enc ? pWcxe : pWcxd;
        const float* Wchside = enc ? pWche : pWchd;

        for (int l = 0; l < LL; l++) {
            int Fi = (l == 0) ? 200 : 64;
            int F = Fi + UU;
            int BF = BB * F;
            float* hl = pH + (long)l * ROWS * UU;

            const float* Wg  = (l == 0) ? Wgside : Wgside + 792*128 + (long)(l-1)*384*128;
            const float* Wcx = (l == 0) ? Wcxside : Wcxside + 3*200*64 + (long)(l-1)*3*64*64;
            const float* Wch = Wchside + (long)l*3*64*64;
            const float* bg = enc ? ((l == 0) ? enc_bg0 : enc_bg + (l-1)*128)
                                  : ((l == 0) ? dec_bg0 : dec_bg + (l-1)*128);
            const float* bc = enc ? ((l == 0) ? enc_bc0 : enc_bc + (l-1)*64)
                                  : ((l == 0) ? dec_bc0 : dec_bc + (l-1)*64);

            int xmode;
            const float* xsrc;
            if (l > 0)      { xmode = 3; xsrc = pH + (long)(l-1) * ROWS * UU; }
            else if (enc)   { xmode = 0; xsrc = inputs; }
            else if (t == 0){ xmode = 2; xsrc = pPROJ; }
            else            { xmode = 1; xsrc = pPROJ; }

            // X0 = [x | h]
            build_cat<<<(ROWS*F)/256, 256>>>(pX, xsrc, xmode, t, hl, Fi);
            // X1 = S @ X0
            gemm_k<0><<<dim3(BF/64, 2), 256>>>(Ssup, 200, 0, 0, pX, BF,
                pX + CHUNK, BF, 200, BF, 200,
                nullptr, nullptr, 0, nullptr, nullptr, nullptr, nullptr, nullptr, 0);
            // X2 = 2*S@X1 - X0
            gemm_k<1><<<dim3(BF/64, 2), 256>>>(Ssup, 200, 0, 0, pX + CHUNK, BF,
                pX + 2*CHUNK, BF, 200, BF, 200,
                nullptr, pX, BF, nullptr, nullptr, nullptr, nullptr, nullptr, 0);
            // gates = sigmoid([X0|X1|X2] @ Wg + bg) -> RH(chunk0) = r*h, U = u
            gemm_k<2><<<dim3(2, 100), 256>>>(pX, F, F, (long)CHUNK, Wg, 128,
                nullptr, 0, ROWS, 128, 3*F,
                bg, nullptr, 0, hl, pRH, pU, nullptr, nullptr, 0);
            // RHD1 = S @ RH
            gemm_k<0><<<dim3(64, 2), 256>>>(Ssup, 200, 0, 0, pRH, 4096,
                RHD1, 4096, 200, 4096, 200,
                nullptr, nullptr, 0, nullptr, nullptr, nullptr, nullptr, nullptr, 0);
            // RHD2 = 2*S@RHD1 - RH
            gemm_k<1><<<dim3(64, 2), 256>>>(Ssup, 200, 0, 0, RHD1, 4096,
                RHD2, 4096, 200, 4096, 200,
                nullptr, pRH, 4096, nullptr, nullptr, nullptr, nullptr, nullptr, 0);
            // T = Xcols(0..Fi) of [X0|X1|X2] @ Wcx   (x-part reuse)
            gemm_k<0><<<dim3(1, 100), 256>>>(pX, F, Fi, (long)CHUNK, Wcx, 64,
                pT, 64, ROWS, 64, 3*Fi,
                nullptr, nullptr, 0, nullptr, nullptr, nullptr, nullptr, nullptr, 0);
            // c = tanh(T + [RH|RHD1|RHD2] @ Wch + bc); h = u*h + (1-u)*c (in place)
            gemm_k<3><<<dim3(1, 100), 256>>>(pRH, 64, 64, (long)RHCH, Wch, 64,
                nullptr, 0, ROWS, 64, 192,
                bc, pT, 64, hl, hl, nullptr, pU, nullptr, 0);
        }

        if (!enc) {
            // projection: out[b,t,:] and next decoder input
            gemm_k<4><<<dim3(4, 100), 256>>>(pH + (long)3 * ROWS * UU, UU, 0, 0,
                proj_W, 200, out, 0, ROWS, 200, UU,
                proj_b, nullptr, 0, nullptr, nullptr, nullptr, nullptr, pPROJ, t);
        }
    }
}

// round 8
// speedup vs baseline: 1.8426x; 1.0635x over previous
#include <cuda_runtime.h>
#include <cuda_bf16.h>
#include <math.h>

// ---------------- problem constants ----------------
#define NN_ 200      // nodes
#define UU  64       // rnn units
#define BB  64       // batch
#define TT  12       // T_IN == T_OUT
#define LL  4
#define ROWS (NN_*BB)        // 12800
#define FMAX 264             // layer0: 200+64
#define CHUNK (ROWS*FMAX)    // floats per chebyshev term (gate buffer)
#define RHCH (ROWS*UU)       // floats per rh chebyshev term

// ---------------- device scratch (static: no runtime allocs) ----------------
__device__ float g_X[3*CHUNK];        // [x0|x1|x2] for gate gconv ([x|h] fused)
__device__ float g_RH[3*RHCH];        // [rh | S@rh | S2@rh - rh]
__device__ float g_T [ROWS*UU];       // candidate x-part partial
__device__ float g_U [ROWS*UU];       // update gate u
__device__ float g_H [LL*ROWS*UU];    // hidden states, rows = n*B+b
__device__ float g_PROJ[BB*NN_*NN_];  // previous decoder projection (B, N*N)
__device__ float g_SS[400*200];       // [S ; 2*S@S] stacked
__device__ float g_Wg_e[792*128 + 3*384*128];
__device__ float g_Wg_d[792*128 + 3*384*128];
__device__ float g_Wcx_e[3*200*64 + 3*(3*64*64)];
__device__ float g_Wcx_d[3*200*64 + 3*(3*64*64)];
__device__ float g_Wch_e[4*(3*64*64)];
__device__ float g_Wch_d[4*(3*64*64)];

// ---------------- small kernels ----------------
__global__ void zerok(float* p, int n) {
    int i = blockIdx.x * 256 + threadIdx.x;
    if (i < n) p[i] = 0.f;
}

__global__ void copyk(const float* __restrict__ s, float* __restrict__ d, int n) {
    int i = blockIdx.x * 256 + threadIdx.x;
    if (i < n) d[i] = s[i];
}

// repack gate weights: src rows (f*3 + k) -> dst rows (k*F + f)
__global__ void wprep(const float* __restrict__ src, float* __restrict__ dst,
                      int F, int out) {
    int idx = blockIdx.x * 256 + threadIdx.x;
    int total = 3 * F * out;
    if (idx >= total) return;
    int c = idx % out;
    int r = idx / out;
    int k = r / F;
    int f = r - k * F;
    dst[idx] = src[(f * 3 + k) * out + c];
}

// repack a feature sub-range [f0, f0+W_) of cand weights into k-major blocks
__global__ void wprep_part(const float* __restrict__ src, float* __restrict__ dst,
                           int f0, int W_, int out) {
    int idx = blockIdx.x * 256 + threadIdx.x;
    int total = 3 * W_ * out;
    if (idx >= total) return;
    int c = idx % out;
    int r = idx / out;
    int k = r / W_;
    int f = r - k * W_;
    dst[idx] = src[((f0 + f) * 3 + k) * out + c];
}

// build concatenated per-node features: dst row (n,b) = [x(Fi) | h(64)]
// xmode: 0 = encoder input (transpose from inputs), 1 = g_PROJ, 2 = zeros,
//        3 = previous layer hidden (rows (n,b), 64)
__global__ void build_cat(float* __restrict__ dst,
                          const float* __restrict__ xsrc, int xmode, int t,
                          const float* __restrict__ st, int Fi) {
    int F = Fi + UU;
    int idx = blockIdx.x * 256 + threadIdx.x;
    int total = ROWS * F;
    if (idx >= total) return;
    int row = idx / F;
    int f = idx - row * F;
    int n = row >> 6, b = row & 63;
    float v;
    if (f < Fi) {
        if (xmode == 0)      v = xsrc[((long)b * TT + t) * 40000 + (long)n * 200 + f];
        else if (xmode == 1) v = xsrc[(long)b * 40000 + (long)n * 200 + f];
        else if (xmode == 2) v = 0.f;
        else                 v = xsrc[row * UU + f];
    } else {
        v = st[row * UU + (f - Fi)];
    }
    dst[(long)row * F + f] = v;
}

// ---------------- fused diffusion kernel (zero padding) --------------------
// SS = [S ; 2*S@S] (400x200). X0 viewed as (200, Ncols) with ld=ldx.
// Writes X1 = S@X0 (rows 0..199 of SS) and X2 = (2S^2)@X0 - X0 (rows 200..399).
// Grid: (Ncols/128, 10). Block 256 threads, tile 40x128, thread tile 5x4.
// Requires: Ncols % 128 == 0 (BF and 4096 both satisfy), K = 200 = 25*8.
#define DBK 8

__global__ __launch_bounds__(256) void diff_k(
    const float* __restrict__ SS,
    const float* __restrict__ X0, int ldx,
    float* __restrict__ X1,
    float* __restrict__ X2)
{
    __shared__ float As[2][DBK][40];
    __shared__ float Bs[2][DBK][128];
    int tid = threadIdx.x;
    int tx = tid & 31, ty = tid >> 5;      // compute: ty row-group (5 rows), tx col-group (4 cols)
    int n0 = blockIdx.x * 128;
    int m0 = blockIdx.y * 40;

    float acc[5][4];
#pragma unroll
    for (int i = 0; i < 5; i++)
#pragma unroll
        for (int j = 0; j < 4; j++) acc[i][j] = 0.f;

    // A loader: 320 elems = 256 (all threads) + 64 (tid<64)
    int a0m = tid >> 3, a0k = tid & 7;
    int a1m = (256 + tid) >> 3, a1k = tid & 7;   // (256+tid)&7 == tid&7
    bool has1 = (tid < 64);

    float ra0, ra1; float4 rb;
    auto fetch = [&](int k0) {
        ra0 = SS[(m0 + a0m) * 200 + k0 + a0k];
        if (has1) ra1 = SS[(m0 + a1m) * 200 + k0 + a1k];
        rb = *reinterpret_cast<const float4*>(&X0[(long)(k0 + ty) * ldx + n0 + tx * 4]);
    };
    auto store_smem = [&](int buf) {
        As[buf][a0k][a0m] = ra0;
        if (has1) As[buf][a1k][a1m] = ra1;
        *reinterpret_cast<float4*>(&Bs[buf][ty][tx * 4]) = rb;
    };

    fetch(0);
    store_smem(0);
    __syncthreads();

    for (int kt = 0; kt < 25; kt++) {
        int cur = kt & 1;
        if (kt < 24) fetch((kt + 1) * DBK);
#pragma unroll
        for (int kk = 0; kk < DBK; kk++) {
            float a[5], b[4];
#pragma unroll
            for (int i = 0; i < 5; i++) a[i] = As[cur][kk][ty * 5 + i];
#pragma unroll
            for (int j = 0; j < 4; j++) b[j] = Bs[cur][kk][tx * 4 + j];
#pragma unroll
            for (int i = 0; i < 5; i++)
#pragma unroll
                for (int j = 0; j < 4; j++) acc[i][j] += a[i] * b[j];
        }
        if (kt < 24) {
            store_smem(cur ^ 1);
            __syncthreads();
        }
    }

    bool first = (m0 < 200);
    int mb = first ? m0 : (m0 - 200);
    int c0 = n0 + tx * 4;
#pragma unroll
    for (int i = 0; i < 5; i++) {
        long base = (long)(mb + ty * 5 + i) * ldx + c0;
        if (first) {
            float4 v = make_float4(acc[i][0], acc[i][1], acc[i][2], acc[i][3]);
            *reinterpret_cast<float4*>(&X1[base]) = v;
        } else {
            float4 x0 = *reinterpret_cast<const float4*>(&X0[base]);
            float4 v = make_float4(acc[i][0] - x0.x, acc[i][1] - x0.y,
                                   acc[i][2] - x0.z, acc[i][3] - x0.w);
            *reinterpret_cast<float4*>(&X2[base]) = v;
        }
    }
}

// ---------------- SGEMM (scalar FFMA, ping-pong smem) with fused epilogues ----
// C(M,Nn) = A(M,K) @ B(K,Nn), row-major.
// Fblk>0: A is 3 equally spaced chunks (stride ablk), each with row-ld=lda and
//         K-width Fblk (columns 0..Fblk-1 of each chunk used).
// MODE: 0 plain, 1 unused, 2 gates (sigmoid -> RH,U),
//       3 cand (tanh(acc+bias+X0addin) -> GRU update in-place), 4 projection,
//       5 scale2 (Cm = 2*v, for S2 prep)
#define BM 128
#define BN 64
#define BK 8

template<int MODE>
__device__ __forceinline__ void epi(
    float v, int gm, int gn,
    float* Cm, int ldc,
    const float* bias, const float* X0, int ldx0,
    const float* H, float* O1, float* O2, const float* Uin,
    float* out2, int t)
{
    if (MODE == 0) {
        Cm[(long)gm * ldc + gn] = v;
    } else if (MODE == 2) {
        float s = 1.f / (1.f + expf(-(v + bias[gn])));
        if (gn < UU) O1[gm * UU + gn] = s * H[gm * UU + gn];   // r*h
        else         O2[gm * UU + gn - UU] = s;                // u
    } else if (MODE == 3) {
        float c = tanhf(v + bias[gn] + X0[(long)gm * ldx0 + gn]);
        float u = Uin[gm * UU + gn];
        O1[gm * UU + gn] = u * H[gm * UU + gn] + (1.f - u) * c;
    } else if (MODE == 4) {  // projection
        float p = v + bias[gn];
        int b_ = gm & 63, n_ = gm >> 6;
        Cm[((long)b_ * TT + t) * 40000 + (long)n_ * 200 + gn] = p;
        out2[(long)b_ * 40000 + (long)n_ * 200 + gn] = p;
    } else if (MODE == 5) {
        Cm[(long)gm * ldc + gn] = 2.f * v;
    }
}

template<int MODE>
__global__ __launch_bounds__(256) void gemm_k(
    const float* __restrict__ A, int lda, int Fblk, long ablk,
    const float* __restrict__ Bm, int ldb,
    float* __restrict__ Cm, int ldc,
    int M, int Nn, int K,
    const float* __restrict__ bias,
    const float* __restrict__ X0, int ldx0,
    const float* __restrict__ H,
    float* __restrict__ O1,
    float* __restrict__ O2,
    const float* __restrict__ Uin,
    float* __restrict__ out2, int t)
{
    __shared__ float As[2][BK][BM];
    __shared__ float Bs[2][BK][BN];
    int tid = threadIdx.x;
    int tx = tid & 15, ty = tid >> 4;
    int m0 = blockIdx.y * BM, n0 = blockIdx.x * BN;

    float acc[8][4];
#pragma unroll
    for (int i = 0; i < 8; i++)
#pragma unroll
        for (int j = 0; j < 4; j++) acc[i][j] = 0.f;

    int la_m = tid >> 2;             // 0..63
    int la_k = (tid & 3) * 2;        // 0,2,4,6
    int lb_r = tid >> 5;             // 0..7
    int lb_c = (tid & 31) * 2;       // 0..62

    int nk = (K + BK - 1) / BK;

    float ra[2][2], rb[2];
    auto fetch = [&](int k0) {
        const float* Ab = A;
        int krel = k0;
        if (Fblk) {
            int kb = k0 / Fblk;
            Ab = A + (long)kb * ablk;
            krel = k0 - kb * Fblk;
        }
#pragma unroll
        for (int mm = 0; mm < 2; mm++) {
            int gm = m0 + la_m + mm * 64;
            float x = 0.f, y = 0.f;
            if (gm < M && krel + la_k < K) {
                const float* p = Ab + (long)gm * lda + krel + la_k;
                x = p[0]; y = p[1];
            }
            ra[mm][0] = x; ra[mm][1] = y;
        }
        {
            float x = 0.f, y = 0.f;
            int gn = n0 + lb_c;
            int gk = k0 + lb_r;
            if (gn < Nn && gk < K) {
                const float* p = Bm + (long)gk * ldb + gn;
                x = p[0]; y = p[1];
            }
            rb[0] = x; rb[1] = y;
        }
    };
    auto store_smem = [&](int buf) {
#pragma unroll
        for (int mm = 0; mm < 2; mm++) {
            As[buf][la_k][la_m + mm * 64] = ra[mm][0];
            As[buf][la_k + 1][la_m + mm * 64] = ra[mm][1];
        }
        Bs[buf][lb_r][lb_c] = rb[0];
        Bs[buf][lb_r][lb_c + 1] = rb[1];
    };

    fetch(0);
    store_smem(0);
    __syncthreads();

    for (int kt = 0; kt < nk; kt++) {
        int cur = kt & 1;
        if (kt + 1 < nk) fetch((kt + 1) * BK);
#pragma unroll
        for (int kk = 0; kk < BK; kk++) {
            float a[8], bb[4];
#pragma unroll
            for (int i = 0; i < 8; i++) a[i] = As[cur][kk][ty * 8 + i];
#pragma unroll
            for (int j = 0; j < 4; j++) bb[j] = Bs[cur][kk][tx * 4 + j];
#pragma unroll
            for (int i = 0; i < 8; i++)
#pragma unroll
                for (int j = 0; j < 4; j++) acc[i][j] += a[i] * bb[j];
        }
        if (kt + 1 < nk) {
            store_smem(cur ^ 1);
            __syncthreads();
        }
    }

#pragma unroll
    for (int i = 0; i < 8; i++) {
        int gm = m0 + ty * 8 + i;
        if (gm >= M) continue;
#pragma unroll
        for (int j = 0; j < 4; j++) {
            int gn = n0 + tx * 4 + j;
            if (gn >= Nn) continue;
            epi<MODE>(acc[i][j], gm, gn, Cm, ldc, bias, X0, ldx0, H, O1, O2, Uin, out2, t);
        }
    }
}

// ---------------- host orchestration ----------------
extern "C" void kernel_launch(void* const* d_in, const int* in_sizes, int n_in,
                              void* d_out, int out_size) {
    (void)in_sizes; (void)n_in; (void)out_size;
    const float* inputs  = (const float*)d_in[0];
    const float* Ssup    = (const float*)d_in[1];
    const float* enc_Wg0 = (const float*)d_in[2];
    const float* enc_bg0 = (const float*)d_in[3];
    const float* enc_Wc0 = (const float*)d_in[4];
    const float* enc_bc0 = (const float*)d_in[5];
    const float* enc_Wg  = (const float*)d_in[6];
    const float* enc_bg  = (const float*)d_in[7];
    const float* enc_Wc  = (const float*)d_in[8];
    const float* enc_bc  = (const float*)d_in[9];
    const float* dec_Wg0 = (const float*)d_in[10];
    const float* dec_bg0 = (const float*)d_in[11];
    const float* dec_Wc0 = (const float*)d_in[12];
    const float* dec_bc0 = (const float*)d_in[13];
    const float* dec_Wg  = (const float*)d_in[14];
    const float* dec_bg  = (const float*)d_in[15];
    const float* dec_Wc  = (const float*)d_in[16];
    const float* dec_bc  = (const float*)d_in[17];
    const float* proj_W  = (const float*)d_in[18];
    const float* proj_b  = (const float*)d_in[19];
    float* out = (float*)d_out;

    float *pX, *pRH, *pT, *pU, *pH, *pPROJ, *pSS;
    float *pWge, *pWgd, *pWcxe, *pWcxd, *pWche, *pWchd;
    cudaGetSymbolAddress((void**)&pX,    g_X);
    cudaGetSymbolAddress((void**)&pRH,   g_RH);
    cudaGetSymbolAddress((void**)&pT,    g_T);
    cudaGetSymbolAddress((void**)&pU,    g_U);
    cudaGetSymbolAddress((void**)&pH,    g_H);
    cudaGetSymbolAddress((void**)&pPROJ, g_PROJ);
    cudaGetSymbolAddress((void**)&pSS,   g_SS);
    cudaGetSymbolAddress((void**)&pWge,  g_Wg_e);
    cudaGetSymbolAddress((void**)&pWgd,  g_Wg_d);
    cudaGetSymbolAddress((void**)&pWcxe, g_Wcx_e);
    cudaGetSymbolAddress((void**)&pWcxd, g_Wcx_d);
    cudaGetSymbolAddress((void**)&pWche, g_Wch_e);
    cudaGetSymbolAddress((void**)&pWchd, g_Wch_d);

    // ---- build SS = [S ; 2*S@S] ----
    copyk<<<(40000 + 255) / 256, 256>>>(Ssup, pSS, 40000);
    gemm_k<5><<<dim3(4, 2), 256>>>(Ssup, 200, 0, 0, Ssup, 200,
        pSS + 40000, 200, 200, 200, 200,
        nullptr, nullptr, 0, nullptr, nullptr, nullptr, nullptr, nullptr, 0);

    // ---- weight repack ----
    wprep<<<(3*264*128)/256, 256>>>(enc_Wg0, pWge, 264, 128);
    wprep<<<(3*264*128)/256, 256>>>(dec_Wg0, pWgd, 264, 128);
    for (int i = 0; i < 3; i++) {
        wprep<<<(3*128*128)/256, 256>>>(enc_Wg + (long)i*384*128,
                                        pWge + 792*128 + (long)i*384*128, 128, 128);
        wprep<<<(3*128*128)/256, 256>>>(dec_Wg + (long)i*384*128,
                                        pWgd + 792*128 + (long)i*384*128, 128, 128);
    }
    wprep_part<<<(3*200*64)/256, 256>>>(enc_Wc0, pWcxe, 0, 200, 64);
    wprep_part<<<(3*200*64)/256, 256>>>(dec_Wc0, pWcxd, 0, 200, 64);
    wprep_part<<<(3*64*64)/256, 256>>>(enc_Wc0, pWche, 200, 64, 64);
    wprep_part<<<(3*64*64)/256, 256>>>(dec_Wc0, pWchd, 200, 64, 64);
    for (int i = 0; i < 3; i++) {
        const float* se = enc_Wc + (long)i*384*64;
        const float* sd = dec_Wc + (long)i*384*64;
        wprep_part<<<(3*64*64)/256, 256>>>(se, pWcxe + 3*200*64 + (long)i*3*64*64, 0, 64, 64);
        wprep_part<<<(3*64*64)/256, 256>>>(sd, pWcxd + 3*200*64 + (long)i*3*64*64, 0, 64, 64);
        wprep_part<<<(3*64*64)/256, 256>>>(se, pWche + (long)(i+1)*3*64*64, 64, 64, 64);
        wprep_part<<<(3*64*64)/256, 256>>>(sd, pWchd + (long)(i+1)*3*64*64, 64, 64, 64);
    }

    // ---- zero initial hidden state ----
    zerok<<<(LL*ROWS*UU)/256, 256>>>(pH, LL*ROWS*UU);

    float* RHD1 = pRH + RHCH;
    float* RHD2 = pRH + 2*RHCH;

    // ---- sequence loop ----
    for (int tg = 0; tg < 2 * TT; tg++) {
        bool enc = (tg < TT);
        int t = enc ? tg : (tg - TT);
        const float* Wgside  = enc ? pWge  : pWgd;
        const float* Wcxside = enc ? pWcxe : pWcxd;
        const float* Wchside = enc ? pWche : pWchd;

        for (int l = 0; l < LL; l++) {
            int Fi = (l == 0) ? 200 : 64;
            int F = Fi + UU;
            int BF = BB * F;
            float* hl = pH + (long)l * ROWS * UU;

            const float* Wg  = (l == 0) ? Wgside : Wgside + 792*128 + (long)(l-1)*384*128;
            const float* Wcx = (l == 0) ? Wcxside : Wcxside + 3*200*64 + (long)(l-1)*3*64*64;
            const float* Wch = Wchside + (long)l*3*64*64;
            const float* bg = enc ? ((l == 0) ? enc_bg0 : enc_bg + (l-1)*128)
                                  : ((l == 0) ? dec_bg0 : dec_bg + (l-1)*128);
            const float* bc = enc ? ((l == 0) ? enc_bc0 : enc_bc + (l-1)*64)
                                  : ((l == 0) ? dec_bc0 : dec_bc + (l-1)*64);

            int xmode;
            const float* xsrc;
            if (l > 0)      { xmode = 3; xsrc = pH + (long)(l-1) * ROWS * UU; }
            else if (enc)   { xmode = 0; xsrc = inputs; }
            else if (t == 0){ xmode = 2; xsrc = pPROJ; }
            else            { xmode = 1; xsrc = pPROJ; }

            // X0 = [x | h]
            build_cat<<<(ROWS*F)/256, 256>>>(pX, xsrc, xmode, t, hl, Fi);
            // X1 = S@X0 ; X2 = (2S^2)@X0 - X0   (fused, zero-padding tiles)
            diff_k<<<dim3(BF/128, 10), 256>>>(pSS, pX, BF, pX + CHUNK, pX + 2*CHUNK);
            // gates = sigmoid([X0|X1|X2] @ Wg + bg) -> RH(chunk0) = r*h, U = u
            gemm_k<2><<<dim3(2, 100), 256>>>(pX, F, F, (long)CHUNK, Wg, 128,
                nullptr, 0, ROWS, 128, 3*F,
                bg, nullptr, 0, hl, pRH, pU, nullptr, nullptr, 0);
            // RHD1 = S@RH ; RHD2 = (2S^2)@RH - RH
            diff_k<<<dim3(32, 10), 256>>>(pSS, pRH, 4096, RHD1, RHD2);
            // T = x-part of [X0|X1|X2] @ Wcx
            gemm_k<0><<<dim3(1, 100), 256>>>(pX, F, Fi, (long)CHUNK, Wcx, 64,
                pT, 64, ROWS, 64, 3*Fi,
                nullptr, nullptr, 0, nullptr, nullptr, nullptr, nullptr, nullptr, 0);
            // c = tanh(T + [RH|RHD1|RHD2] @ Wch + bc); h = u*h + (1-u)*c (in place)
            gemm_k<3><<<dim3(1, 100), 256>>>(pRH, 64, 64, (long)RHCH, Wch, 64,
                nullptr, 0, ROWS, 64, 192,
                bc, pT, 64, hl, hl, nullptr, pU, nullptr, 0);
        }

        if (!enc) {
            // projection: out[b,t,:] and next decoder input
            gemm_k<4><<<dim3(4, 100), 256>>>(pH + (long)3 * ROWS * UU, UU, 0, 0,
                proj_W, 200, out, 0, ROWS, 200, UU,
                proj_b, nullptr, 0, nullptr, nullptr, nullptr, nullptr, pPROJ, t);
        }
    }
}

// round 11
// speedup vs baseline: 2.3523x; 1.2766x over previous
#include <cuda_runtime.h>
#include <cuda_bf16.h>
#include <math.h>
#include <stdint.h>

// ---------------- problem constants ----------------
#define NN_ 200
#define UU  64
#define BB  64
#define TT  12
#define LL  4
#define ROWS (NN_*BB)        // 12800
#define FMAX 264
#define CHUNK (ROWS*FMAX)
#define RHCH (ROWS*UU)

// ---------------- device scratch ----------------
__device__ float g_X[3*CHUNK];        // [x0|x1|x2] gate gconv ([x|h]), ld=F
__device__ float g_RH[3*RHCH];        // [rh | S@rh | 2S^2rh - rh]
__device__ float g_T [ROWS*UU];
__device__ float g_U [ROWS*UU];
__device__ float g_H [LL*ROWS*UU];
__device__ float g_PROJ[BB*NN_*NN_];
__device__ float g_SS[400*200];       // [S ; 2*S@S] fp32
__device__ unsigned short g_SSh[512*208], g_SSl[512*208];  // split bf16, padded

// split-bf16 transposed weights [n][Kpad]
#define GWSZ (128*800 + 3*128*384)
#define CXSZ (64*608 + 3*64*192)
#define CHSZ (4*64*192)
#define PRSZ (256*64)
__device__ unsigned short g_Bgh_e[GWSZ], g_Bgl_e[GWSZ], g_Bgh_d[GWSZ], g_Bgl_d[GWSZ];
__device__ unsigned short g_Bcxh_e[CXSZ], g_Bcxl_e[CXSZ], g_Bcxh_d[CXSZ], g_Bcxl_d[CXSZ];
__device__ unsigned short g_Bchh_e[CHSZ], g_Bchl_e[CHSZ], g_Bchh_d[CHSZ], g_Bchl_d[CHSZ];
__device__ unsigned short g_Bph[PRSZ], g_Bpl[PRSZ];

// ---------------- helpers ----------------
__device__ __forceinline__ uint32_t smem_u32(const void* p) {
    uint32_t a;
    asm("{ .reg .u64 t; cvta.to.shared.u64 t, %1; cvt.u32.u64 %0, t; }" : "=r"(a) : "l"(p));
    return a;
}
__device__ __forceinline__ void ldm_x4(uint32_t a, uint32_t& r0, uint32_t& r1,
                                       uint32_t& r2, uint32_t& r3) {
    asm volatile("ldmatrix.sync.aligned.m8n8.x4.shared.b16 {%0,%1,%2,%3}, [%4];"
                 : "=r"(r0), "=r"(r1), "=r"(r2), "=r"(r3) : "r"(a));
}
__device__ __forceinline__ void ldm_x2(uint32_t a, uint32_t& r0, uint32_t& r1) {
    asm volatile("ldmatrix.sync.aligned.m8n8.x2.shared.b16 {%0,%1}, [%2];"
                 : "=r"(r0), "=r"(r1) : "r"(a));
}
__device__ __forceinline__ void mma16816(float* c, const uint32_t* a, const uint32_t* b) {
    asm volatile("mma.sync.aligned.m16n8k16.row.col.f32.bf16.bf16.f32 "
                 "{%0,%1,%2,%3}, {%4,%5,%6,%7}, {%8,%9}, {%0,%1,%2,%3};"
                 : "+f"(c[0]), "+f"(c[1]), "+f"(c[2]), "+f"(c[3])
                 : "r"(a[0]), "r"(a[1]), "r"(a[2]), "r"(a[3]), "r"(b[0]), "r"(b[1]));
}
__device__ __forceinline__ void split_bf16(float v, unsigned short& h, unsigned short& l) {
    __nv_bfloat16 hb = __float2bfloat16(v);
    float hf = __bfloat162float(hb);
    __nv_bfloat16 lb = __float2bfloat16(v - hf);
    h = __bfloat16_as_ushort(hb);
    l = __bfloat16_as_ushort(lb);
}

// ---------------- small kernels ----------------
__global__ void zerok(float* p, int n) {
    int i = blockIdx.x * 256 + threadIdx.x;
    if (i < n) p[i] = 0.f;
}
__global__ void copyk(const float* __restrict__ s, float* __restrict__ d, int n) {
    int i = blockIdx.x * 256 + threadIdx.x;
    if (i < n) d[i] = s[i];
}

// build X0 = [x | h], ld = F
__global__ void build_cat(float* __restrict__ dst,
                          const float* __restrict__ xsrc, int xmode, int t,
                          const float* __restrict__ st, int Fi) {
    int F = Fi + UU;
    int idx = blockIdx.x * 256 + threadIdx.x;
    if (idx >= ROWS * F) return;
    int row = idx / F;
    int f = idx - row * F;
    int n = row >> 6, b = row & 63;
    float v;
    if (f < Fi) {
        if (xmode == 0)      v = xsrc[((long)b * TT + t) * 40000 + (long)n * 200 + f];
        else if (xmode == 1) v = xsrc[(long)b * 40000 + (long)n * 200 + f];
        else if (xmode == 2) v = 0.f;
        else                 v = xsrc[row * UU + f];
    } else {
        v = st[row * UU + (f - Fi)];
    }
    dst[(long)row * F + f] = v;
}

// s2 prep: out = 2*S@S (200x200), FFMA (one-time, exact)
#define DBK 8
__global__ __launch_bounds__(256) void s2_k(const float* __restrict__ S,
                                            float* __restrict__ out) {
    __shared__ float As[DBK][40];
    __shared__ float Bs[DBK][128];
    int tid = threadIdx.x;
    int tx = tid & 31, ty = tid >> 5;
    int n0 = blockIdx.x * 128;
    int m0 = blockIdx.y * 40;
    float acc[5][4];
#pragma unroll
    for (int i = 0; i < 5; i++)
#pragma unroll
        for (int j = 0; j < 4; j++) acc[i][j] = 0.f;
    for (int k0 = 0; k0 < 200; k0 += DBK) {
        As[tid & 7][tid >> 3] = S[(m0 + (tid >> 3)) * 200 + k0 + (tid & 7)];
        if (tid < 64) As[tid & 7][(256 + tid) >> 3] = S[(m0 + ((256 + tid) >> 3)) * 200 + k0 + (tid & 7)];
        float4 b4 = make_float4(0.f, 0.f, 0.f, 0.f);
        int gn = n0 + tx * 4;
        if (gn < 200) {
            const float* p = &S[(k0 + ty) * 200 + gn];
            b4.x = p[0]; b4.y = (gn + 1 < 200) ? p[1] : 0.f;
            b4.z = (gn + 2 < 200) ? p[2] : 0.f; b4.w = (gn + 3 < 200) ? p[3] : 0.f;
        }
        *reinterpret_cast<float4*>(&Bs[ty][tx * 4]) = b4;
        __syncthreads();
#pragma unroll
        for (int kk = 0; kk < DBK; kk++) {
            float a[5], b[4];
#pragma unroll
            for (int i = 0; i < 5; i++) a[i] = As[kk][ty * 5 + i];
#pragma unroll
            for (int j = 0; j < 4; j++) b[j] = Bs[kk][tx * 4 + j];
#pragma unroll
            for (int i = 0; i < 5; i++)
#pragma unroll
                for (int j = 0; j < 4; j++) acc[i][j] += a[i] * b[j];
        }
        __syncthreads();
    }
#pragma unroll
    for (int i = 0; i < 5; i++) {
        int gm = m0 + ty * 5 + i;
#pragma unroll
        for (int j = 0; j < 4; j++) {
            int gn = n0 + tx * 4 + j;
            if (gm < 200 && gn < 200) out[gm * 200 + gn] = 2.f * acc[i][j];
        }
    }
}

// split SS (400x200 fp32) -> 512x208 bf16 hi/lo zero-padded
__global__ void ssplit(const float* __restrict__ SS,
                       unsigned short* __restrict__ dh, unsigned short* __restrict__ dl) {
    int idx = blockIdx.x * 256 + threadIdx.x;
    if (idx >= 512 * 208) return;
    int m = idx / 208, k = idx - m * 208;
    float v = (m < 400 && k < 200) ? SS[m * 200 + k] : 0.f;
    unsigned short h, l;
    split_bf16(v, h, l);
    dh[idx] = h; dl[idx] = l;
}

// weight split transposed: dst[n][kb*Fw+f] = src[((foff+f)*3+kb)*ldsrc + n]
__global__ void wsplitT(const float* __restrict__ src, int ldsrc, int foff, int Fw,
                        int Kpad, int Npad, int Nsrc,
                        unsigned short* __restrict__ dh, unsigned short* __restrict__ dl) {
    int idx = blockIdx.x * 256 + threadIdx.x;
    if (idx >= Npad * Kpad) return;
    int n = idx / Kpad;
    int r = idx - n * Kpad;
    float v = 0.f;
    if (r < 3 * Fw && n < Nsrc) {
        int kb = r / Fw, f = r - kb * Fw;
        v = src[((long)(foff + f) * 3 + kb) * ldsrc + n];
    }
    unsigned short h, l;
    split_bf16(v, h, l);
    dh[idx] = h; dl[idx] = l;
}
__global__ void wsplit_proj(const float* __restrict__ src,
                            unsigned short* __restrict__ dh, unsigned short* __restrict__ dl) {
    int idx = blockIdx.x * 256 + threadIdx.x;
    if (idx >= 256 * 64) return;
    int n = idx >> 6, k = idx & 63;
    float v = (n < 200) ? src[k * 200 + n] : 0.f;
    unsigned short h, l;
    split_bf16(v, h, l);
    dh[idx] = h; dl[idx] = l;
}

#define ALD 24
#define BLD 24

// ---------------- mma diffusion kernel ----------------
// A = presplit [S;2S^2] (512x208 bf16), B = X0 (200 x cols fp32, ld=ldx).
// rows<200 -> X1 = S@X0 ; rows 200..399 -> X2 = (2S^2)@X0 - X0.
__global__ __launch_bounds__(256) void diffmma(
    const unsigned short* __restrict__ SSh, const unsigned short* __restrict__ SSl,
    const float* __restrict__ X0, int ldx,
    float* __restrict__ X1, float* __restrict__ X2)
{
    __shared__ __align__(16) unsigned short Ah[2][128][ALD], Al[2][128][ALD];
    __shared__ __align__(16) unsigned short Bh[2][64][BLD], Bl[2][64][BLD];
    int tid = threadIdx.x, wid = tid >> 5, lane = tid & 31;
    int wm = wid >> 1, wn = wid & 1;
    int m0 = blockIdx.y * 128, n0 = blockIdx.x * 64;

    float acc[2][4][4];
#pragma unroll
    for (int i = 0; i < 2; i++)
#pragma unroll
        for (int j = 0; j < 4; j++)
#pragma unroll
            for (int q = 0; q < 4; q++) acc[i][j][q] = 0.f;

    uint32_t sAh = smem_u32(Ah), sAl = smem_u32(Al);
    uint32_t sBh = smem_u32(Bh), sBl = smem_u32(Bl);
    int lr = (lane & 7) + ((lane >> 3) & 1) * 8;
    int lc = (lane >> 4) * 8;
    int br7 = lane & 7, bsel = (lane >> 3) & 1;

    int ar = tid >> 1, ak8 = (tid & 1) * 8;
    int bk = tid >> 4, bn4 = (tid & 15) * 4;

    uint4 rah, ral; float4 rbv;
    auto fetch = [&](int k0) {
        rah = *reinterpret_cast<const uint4*>(SSh + (long)(m0 + ar) * 208 + k0 + ak8);
        ral = *reinterpret_cast<const uint4*>(SSl + (long)(m0 + ar) * 208 + k0 + ak8);
        int k = k0 + bk;
        rbv = (k < 200) ? *reinterpret_cast<const float4*>(&X0[(long)k * ldx + n0 + bn4])
                        : make_float4(0.f, 0.f, 0.f, 0.f);
    };
    auto store = [&](int buf) {
        *reinterpret_cast<uint4*>(&Ah[buf][ar][ak8]) = rah;
        *reinterpret_cast<uint4*>(&Al[buf][ar][ak8]) = ral;
        float vv[4] = {rbv.x, rbv.y, rbv.z, rbv.w};
#pragma unroll
        for (int j = 0; j < 4; j++) {
            unsigned short h, l;
            split_bf16(vv[j], h, l);
            Bh[buf][bn4 + j][bk] = h;
            Bl[buf][bn4 + j][bk] = l;
        }
    };

    fetch(0); store(0); __syncthreads();
    const int nk = 13;
    for (int kt = 0; kt < nk; kt++) {
        int cur = kt & 1;
        if (kt + 1 < nk) fetch((kt + 1) * 16);
        uint32_t ah[2][4], al[2][4], bh[4][2], bl[4][2];
#pragma unroll
        for (int mi = 0; mi < 2; mi++) {
            uint32_t off = (uint32_t)(((cur * 128 + wm * 32 + mi * 16 + lr) * ALD + lc) * 2);
            ldm_x4(sAh + off, ah[mi][0], ah[mi][1], ah[mi][2], ah[mi][3]);
            ldm_x4(sAl + off, al[mi][0], al[mi][1], al[mi][2], al[mi][3]);
        }
#pragma unroll
        for (int nf = 0; nf < 4; nf++) {
            uint32_t off = (uint32_t)(((cur * 64 + wn * 32 + nf * 8 + br7) * BLD + bsel * 8) * 2);
            ldm_x2(sBh + off, bh[nf][0], bh[nf][1]);
            ldm_x2(sBl + off, bl[nf][0], bl[nf][1]);
        }
#pragma unroll
        for (int mi = 0; mi < 2; mi++)
#pragma unroll
            for (int nf = 0; nf < 4; nf++) {
                mma16816(acc[mi][nf], ah[mi], bh[nf]);
                mma16816(acc[mi][nf], al[mi], bh[nf]);
                mma16816(acc[mi][nf], ah[mi], bl[nf]);
            }
        if (kt + 1 < nk) { store(cur ^ 1); __syncthreads(); }
    }

    int g = lane >> 2, tq = lane & 3;
#pragma unroll
    for (int mi = 0; mi < 2; mi++) {
#pragma unroll
        for (int nf = 0; nf < 4; nf++) {
            int cn = n0 + wn * 32 + nf * 8 + 2 * tq;
#pragma unroll
            for (int e = 0; e < 4; e++) {
                int gm = m0 + wm * 32 + mi * 16 + g + (e >> 1) * 8;
                int cc = cn + (e & 1);
                float v = acc[mi][nf][e];
                if (gm < 200) {
                    X1[(long)gm * ldx + cc] = v;
                } else if (gm < 400) {
                    long p = (long)(gm - 200) * ldx + cc;
                    X2[p] = v - X0[p];
                }
            }
        }
    }
}

// ---------------- mma feature GEMM with fused epilogues ----------------
// D(12800, Nn) = A(fp32 chunked) @ B^T(presplit bf16 [n][Kpad]).
// MODE: 0 plain->O1(ld 64), 2 gates, 3 cand+GRU, 4 projection
template<int MODE>
__device__ __forceinline__ void epi(float v, int gm, int cn,
    const float* bias, const float* add_, const float* H,
    float* O1, float* O2, const float* Uin, int t)
{
    if (MODE == 0) {
        O1[gm * UU + cn] = v;
    } else if (MODE == 2) {
        float s = 1.f / (1.f + expf(-(v + bias[cn])));
        if (cn < UU) O1[gm * UU + cn] = s * H[gm * UU + cn];
        else         O2[gm * UU + cn - UU] = s;
    } else if (MODE == 3) {
        float c = tanhf(v + bias[cn] + add_[gm * UU + cn]);
        float u = Uin[gm * UU + cn];
        O1[gm * UU + cn] = u * H[gm * UU + cn] + (1.f - u) * c;
    } else if (MODE == 4) {
        if (cn < 200) {
            float p = v + bias[cn];
            int b_ = gm & 63, n_ = gm >> 6;
            O1[((long)b_ * TT + t) * 40000 + (long)n_ * 200 + cn] = p;
            O2[(long)b_ * 40000 + (long)n_ * 200 + cn] = p;
        }
    }
}

template<int MODE>
__global__ __launch_bounds__(256) void featmma(
    const float* __restrict__ A, int lda, int Fblk, long ablk, int K,
    const unsigned short* __restrict__ Bgh, const unsigned short* __restrict__ Bgl, int Kpad,
    int Nn,
    const float* __restrict__ bias, const float* __restrict__ add_,
    const float* __restrict__ H, float* __restrict__ O1, float* __restrict__ O2,
    const float* __restrict__ Uin, int t)
{
    __shared__ __align__(16) unsigned short Ah[2][128][ALD], Al[2][128][ALD];
    __shared__ __align__(16) unsigned short Bh[2][64][BLD], Bl[2][64][BLD];
    int tid = threadIdx.x, wid = tid >> 5, lane = tid & 31;
    int wm = wid >> 1, wn = wid & 1;
    int m0 = blockIdx.y * 128, n0 = blockIdx.x * 64;

    float acc[2][4][4];
#pragma unroll
    for (int i = 0; i < 2; i++)
#pragma unroll
        for (int j = 0; j < 4; j++)
#pragma unroll
            for (int q = 0; q < 4; q++) acc[i][j][q] = 0.f;

    uint32_t sAh = smem_u32(Ah), sAl = smem_u32(Al);
    uint32_t sBh = smem_u32(Bh), sBl = smem_u32(Bl);
    int lr = (lane & 7) + ((lane >> 3) & 1) * 8;
    int lc = (lane >> 4) * 8;
    int br7 = lane & 7, bsel = (lane >> 3) & 1;

    int ar = tid >> 1, ak8 = (tid & 1) * 8;
    int bn = tid >> 2, bk4 = (tid & 3) * 4;

    float va[8]; uint2 rbh, rbl;
    auto fetch = [&](int k0) {
#pragma unroll
        for (int i = 0; i < 8; i++) {
            int k = k0 + ak8 + i;
            float v = 0.f;
            if (k < K) {
                int kb = (k >= Fblk) + (k >= 2 * Fblk);
                int krel = k - kb * Fblk;
                v = A[(long)kb * ablk + (long)(m0 + ar) * lda + krel];
            }
            va[i] = v;
        }
        long boff = (long)(n0 + bn) * Kpad + k0 + bk4;
        rbh = *reinterpret_cast<const uint2*>(Bgh + boff);
        rbl = *reinterpret_cast<const uint2*>(Bgl + boff);
    };
    auto store = [&](int buf) {
        unsigned short hs[8], ls[8];
#pragma unroll
        for (int i = 0; i < 8; i++) split_bf16(va[i], hs[i], ls[i]);
        uint4 hq, lq;
        hq.x = (uint32_t)hs[0] | ((uint32_t)hs[1] << 16);
        hq.y = (uint32_t)hs[2] | ((uint32_t)hs[3] << 16);
        hq.z = (uint32_t)hs[4] | ((uint32_t)hs[5] << 16);
        hq.w = (uint32_t)hs[6] | ((uint32_t)hs[7] << 16);
        lq.x = (uint32_t)ls[0] | ((uint32_t)ls[1] << 16);
        lq.y = (uint32_t)ls[2] | ((uint32_t)ls[3] << 16);
        lq.z = (uint32_t)ls[4] | ((uint32_t)ls[5] << 16);
        lq.w = (uint32_t)ls[6] | ((uint32_t)ls[7] << 16);
        *reinterpret_cast<uint4*>(&Ah[buf][ar][ak8]) = hq;
        *reinterpret_cast<uint4*>(&Al[buf][ar][ak8]) = lq;
        *reinterpret_cast<uint2*>(&Bh[buf][bn][bk4]) = rbh;
        *reinterpret_cast<uint2*>(&Bl[buf][bn][bk4]) = rbl;
    };

    int nk = (K + 15) / 16;
    fetch(0); store(0); __syncthreads();
    for (int kt = 0; kt < nk; kt++) {
        int cur = kt & 1;
        if (kt + 1 < nk) fetch((kt + 1) * 16);
        uint32_t ah[2][4], al[2][4], bh[4][2], bl[4][2];
#pragma unroll
        for (int mi = 0; mi < 2; mi++) {
            uint32_t off = (uint32_t)(((cur * 128 + wm * 32 + mi * 16 + lr) * ALD + lc) * 2);
            ldm_x4(sAh + off, ah[mi][0], ah[mi][1], ah[mi][2], ah[mi][3]);
            ldm_x4(sAl + off, al[mi][0], al[mi][1], al[mi][2], al[mi][3]);
        }
#pragma unroll
        for (int nf = 0; nf < 4; nf++) {
            uint32_t off = (uint32_t)(((cur * 64 + wn * 32 + nf * 8 + br7) * BLD + bsel * 8) * 2);
            ldm_x2(sBh + off, bh[nf][0], bh[nf][1]);
            ldm_x2(sBl + off, bl[nf][0], bl[nf][1]);
        }
#pragma unroll
        for (int mi = 0; mi < 2; mi++)
#pragma unroll
            for (int nf = 0; nf < 4; nf++) {
                mma16816(acc[mi][nf], ah[mi], bh[nf]);
                mma16816(acc[mi][nf], al[mi], bh[nf]);
                mma16816(acc[mi][nf], ah[mi], bl[nf]);
            }
        if (kt + 1 < nk) { store(cur ^ 1); __syncthreads(); }
    }

    int g = lane >> 2, tq = lane & 3;
#pragma unroll
    for (int mi = 0; mi < 2; mi++)
#pragma unroll
        for (int nf = 0; nf < 4; nf++) {
            int cn = n0 + wn * 32 + nf * 8 + 2 * tq;
#pragma unroll
            for (int e = 0; e < 4; e++) {
                int gm = m0 + wm * 32 + mi * 16 + g + (e >> 1) * 8;
                int cc = cn + (e & 1);
                if (cc < Nn)
                    epi<MODE>(acc[mi][nf][e], gm, cc, bias, add_, H, O1, O2, Uin, t);
            }
        }
}

// ---------------- host orchestration ----------------
extern "C" void kernel_launch(void* const* d_in, const int* in_sizes, int n_in,
                              void* d_out, int out_size) {
    (void)in_sizes; (void)n_in; (void)out_size;
    const float* inputs  = (const float*)d_in[0];
    const float* Ssup    = (const float*)d_in[1];
    const float* enc_Wg0 = (const float*)d_in[2];
    const float* enc_bg0 = (const float*)d_in[3];
    const float* enc_Wc0 = (const float*)d_in[4];
    const float* enc_bc0 = (const float*)d_in[5];
    const float* enc_Wg  = (const float*)d_in[6];
    const float* enc_bg  = (const float*)d_in[7];
    const float* enc_Wc  = (const float*)d_in[8];
    const float* enc_bc  = (const float*)d_in[9];
    const float* dec_Wg0 = (const float*)d_in[10];
    const float* dec_bg0 = (const float*)d_in[11];
    const float* dec_Wc0 = (const float*)d_in[12];
    const float* dec_bc0 = (const float*)d_in[13];
    const float* dec_Wg  = (const float*)d_in[14];
    const float* dec_bg  = (const float*)d_in[15];
    const float* dec_Wc  = (const float*)d_in[16];
    const float* dec_bc  = (const float*)d_in[17];
    const float* proj_W  = (const float*)d_in[18];
    const float* proj_b  = (const float*)d_in[19];
    float* out = (float*)d_out;

    float *pX, *pRH, *pT, *pU, *pH, *pPROJ, *pSS;
    cudaGetSymbolAddress((void**)&pX,    g_X);
    cudaGetSymbolAddress((void**)&pRH,   g_RH);
    cudaGetSymbolAddress((void**)&pT,    g_T);
    cudaGetSymbolAddress((void**)&pU,    g_U);
    cudaGetSymbolAddress((void**)&pH,    g_H);
    cudaGetSymbolAddress((void**)&pPROJ, g_PROJ);
    cudaGetSymbolAddress((void**)&pSS,   g_SS);
    unsigned short *pSSh, *pSSl, *pBph, *pBpl;
    cudaGetSymbolAddress((void**)&pSSh, g_SSh);
    cudaGetSymbolAddress((void**)&pSSl, g_SSl);
    cudaGetSymbolAddress((void**)&pBph, g_Bph);
    cudaGetSymbolAddress((void**)&pBpl, g_Bpl);
    unsigned short *pBgh[2], *pBgl[2], *pBcxh[2], *pBcxl[2], *pBchh[2], *pBchl[2];
    cudaGetSymbolAddress((void**)&pBgh[0], g_Bgh_e); cudaGetSymbolAddress((void**)&pBgl[0], g_Bgl_e);
    cudaGetSymbolAddress((void**)&pBgh[1], g_Bgh_d); cudaGetSymbolAddress((void**)&pBgl[1], g_Bgl_d);
    cudaGetSymbolAddress((void**)&pBcxh[0], g_Bcxh_e); cudaGetSymbolAddress((void**)&pBcxl[0], g_Bcxl_e);
    cudaGetSymbolAddress((void**)&pBcxh[1], g_Bcxh_d); cudaGetSymbolAddress((void**)&pBcxl[1], g_Bcxl_d);
    cudaGetSymbolAddress((void**)&pBchh[0], g_Bchh_e); cudaGetSymbolAddress((void**)&pBchl[0], g_Bchl_e);
    cudaGetSymbolAddress((void**)&pBchh[1], g_Bchh_d); cudaGetSymbolAddress((void**)&pBchl[1], g_Bchl_d);

    // ---- prep: SS = [S ; 2S^2], split ----
    copyk<<<(40000 + 255) / 256, 256>>>(Ssup, pSS, 40000);
    s2_k<<<dim3(2, 5), 256>>>(Ssup, pSS + 40000);
    ssplit<<<(512 * 208 + 255) / 256, 256>>>(pSS, pSSh, pSSl);

    // ---- weight splits ----
    const float* Wg0s[2] = {enc_Wg0, dec_Wg0};
    const float* Wgs[2]  = {enc_Wg,  dec_Wg};
    const float* Wc0s[2] = {enc_Wc0, dec_Wc0};
    const float* Wcs[2]  = {enc_Wc,  dec_Wc};
    for (int s = 0; s < 2; s++) {
        wsplitT<<<(128 * 800 + 255) / 256, 256>>>(Wg0s[s], 128, 0, 264, 800, 128, 128,
                                                  pBgh[s], pBgl[s]);
        wsplitT<<<(64 * 608 + 255) / 256, 256>>>(Wc0s[s], 64, 0, 200, 608, 64, 64,
                                                 pBcxh[s], pBcxl[s]);
        wsplitT<<<(64 * 192 + 255) / 256, 256>>>(Wc0s[s], 64, 200, 64, 192, 64, 64,
                                                 pBchh[s], pBchl[s]);
        for (int i = 0; i < 3; i++) {
            wsplitT<<<(128 * 384 + 255) / 256, 256>>>(Wgs[s] + (long)i * 384 * 128, 128, 0, 128,
                384, 128, 128, pBgh[s] + 128 * 800 + (long)i * 128 * 384,
                pBgl[s] + 128 * 800 + (long)i * 128 * 384);
            wsplitT<<<(64 * 192 + 255) / 256, 256>>>(Wcs[s] + (long)i * 384 * 64, 64, 0, 64,
                192, 64, 64, pBcxh[s] + 64 * 608 + (long)i * 64 * 192,
                pBcxl[s] + 64 * 608 + (long)i * 64 * 192);
            wsplitT<<<(64 * 192 + 255) / 256, 256>>>(Wcs[s] + (long)i * 384 * 64, 64, 64, 64,
                192, 64, 64, pBchh[s] + (long)(i + 1) * 64 * 192,
                pBchl[s] + (long)(i + 1) * 64 * 192);
        }
    }
    wsplit_proj<<<64, 256>>>(proj_W, pBph, pBpl);

    // ---- zero initial hidden ----
    zerok<<<(LL * ROWS * UU) / 256, 256>>>(pH, LL * ROWS * UU);

    float* RHD1 = pRH + RHCH;
    float* RHD2 = pRH + 2 * RHCH;

    // ---- sequence loop ----
    for (int tg = 0; tg < 2 * TT; tg++) {
        bool enc = (tg < TT);
        int side = enc ? 0 : 1;
        int t = enc ? tg : (tg - TT);

        for (int l = 0; l < LL; l++) {
            int Fi = (l == 0) ? 200 : 64;
            int F = Fi + UU;
            int BF = BB * F;
            float* hl = pH + (long)l * ROWS * UU;

            const unsigned short* Bgh = pBgh[side] + ((l == 0) ? 0 : 128 * 800 + (long)(l - 1) * 128 * 384);
            const unsigned short* Bgl = pBgl[side] + ((l == 0) ? 0 : 128 * 800 + (long)(l - 1) * 128 * 384);
            int Kpg = (l == 0) ? 800 : 384;
            const unsigned short* Bcxh = pBcxh[side] + ((l == 0) ? 0 : 64 * 608 + (long)(l - 1) * 64 * 192);
            const unsigned short* Bcxl = pBcxl[side] + ((l == 0) ? 0 : 64 * 608 + (long)(l - 1) * 64 * 192);
            int Kpx = (l == 0) ? 608 : 192;
            const unsigned short* Bchh = pBchh[side] + (long)l * 64 * 192;
            const unsigned short* Bchl = pBchl[side] + (long)l * 64 * 192;
            const float* bg = enc ? ((l == 0) ? enc_bg0 : enc_bg + (l - 1) * 128)
                                  : ((l == 0) ? dec_bg0 : dec_bg + (l - 1) * 128);
            const float* bc = enc ? ((l == 0) ? enc_bc0 : enc_bc + (l - 1) * 64)
                                  : ((l == 0) ? dec_bc0 : dec_bc + (l - 1) * 64);

            int xmode;
            const float* xsrc;
            if (l > 0)       { xmode = 3; xsrc = pH + (long)(l - 1) * ROWS * UU; }
            else if (enc)    { xmode = 0; xsrc = inputs; }
            else if (t == 0) { xmode = 2; xsrc = pPROJ; }
            else             { xmode = 1; xsrc = pPROJ; }

            build_cat<<<(ROWS * F) / 256, 256>>>(pX, xsrc, xmode, t, hl, Fi);
            diffmma<<<dim3(BF / 64, 4), 256>>>(pSSh, pSSl, pX, BF, pX + CHUNK, pX + 2 * CHUNK);
            featmma<2><<<dim3(2, 100), 256>>>(pX, F, F, (long)CHUNK, 3 * F,
                Bgh, Bgl, Kpg, 128, bg, nullptr, hl, pRH, pU, nullptr, 0);
            diffmma<<<dim3(64, 4), 256>>>(pSSh, pSSl, pRH, 4096, RHD1, RHD2);
            featmma<0><<<dim3(1, 100), 256>>>(pX, F, Fi, (long)CHUNK, 3 * Fi,
                Bcxh, Bcxl, Kpx, 64, nullptr, nullptr, nullptr, pT, nullptr, nullptr, 0);
            featmma<3><<<dim3(1, 100), 256>>>(pRH, 64, 64, (long)RHCH, 192,
                Bchh, Bchl, 192, 64, bc, pT, hl, hl, nullptr, pU, 0);
        }

        if (!enc) {
            featmma<4><<<dim3(4, 100), 256>>>(pH + (long)3 * ROWS * UU, 64, 64, 0, 64,
                pBph, pBpl, 64, 200, proj_b, nullptr, nullptr, out, pPROJ, nullptr, t);
        }
    }
}

// round 12
// speedup vs baseline: 2.5567x; 1.0869x over previous
#include <cuda_runtime.h>
#include <cuda_bf16.h>
#include <math.h>
#include <stdint.h>

// ---------------- problem constants ----------------
#define NN_ 200
#define UU  64
#define BB  64
#define TT  12
#define LL  4
#define ROWS (NN_*BB)        // 12800
#define FMAX 264
#define CHUNK (ROWS*FMAX)    // chunk stride (elements) in X arrays
#define RHCH (ROWS*UU)

typedef unsigned short ush;

// ---------------- device scratch ----------------
// activations stored as split bf16 (hi, lo)
__device__ ush g_Xh[3*CHUNK], g_Xl[3*CHUNK];      // [x0|x1|x2], ld=F
__device__ ush g_RHh[3*RHCH], g_RHl[3*RHCH];      // [rh | S rh | 2S^2 rh - rh]
__device__ ush g_h3h[ROWS*UU], g_h3l[ROWS*UU];    // split copy of h layer3
__device__ float g_U [ROWS*UU];                   // update gate u (fp32)
__device__ float g_H [LL*ROWS*UU];                // hidden states fp32
__device__ float g_PROJ[BB*NN_*NN_];
__device__ float g_SS[400*200];                   // [S ; 2*S@S] fp32
__device__ ush g_SSh[512*208], g_SSl[512*208];    // split, padded

// weights: split-bf16 transposed [n][Kpad]
#define GWSZ (128*800 + 3*128*384)
#define CWSZ (64*800 + 3*64*384)
#define PRSZ (256*64)
__device__ ush g_Bgh_e[GWSZ], g_Bgl_e[GWSZ], g_Bgh_d[GWSZ], g_Bgl_d[GWSZ];
__device__ ush g_Bch_e[CWSZ], g_Bcl_e[CWSZ], g_Bch_d[CWSZ], g_Bcl_d[CWSZ];
__device__ ush g_Bph[PRSZ], g_Bpl[PRSZ];

// ---------------- helpers ----------------
__device__ __forceinline__ uint32_t smem_u32(const void* p) {
    uint32_t a;
    asm("{ .reg .u64 t; cvta.to.shared.u64 t, %1; cvt.u32.u64 %0, t; }" : "=r"(a) : "l"(p));
    return a;
}
__device__ __forceinline__ void ldm_x4(uint32_t a, uint32_t& r0, uint32_t& r1,
                                       uint32_t& r2, uint32_t& r3) {
    asm volatile("ldmatrix.sync.aligned.m8n8.x4.shared.b16 {%0,%1,%2,%3}, [%4];"
                 : "=r"(r0), "=r"(r1), "=r"(r2), "=r"(r3) : "r"(a));
}
__device__ __forceinline__ void ldm_x2(uint32_t a, uint32_t& r0, uint32_t& r1) {
    asm volatile("ldmatrix.sync.aligned.m8n8.x2.shared.b16 {%0,%1}, [%2];"
                 : "=r"(r0), "=r"(r1) : "r"(a));
}
__device__ __forceinline__ void mma16816(float* c, const uint32_t* a, const uint32_t* b) {
    asm volatile("mma.sync.aligned.m16n8k16.row.col.f32.bf16.bf16.f32 "
                 "{%0,%1,%2,%3}, {%4,%5,%6,%7}, {%8,%9}, {%0,%1,%2,%3};"
                 : "+f"(c[0]), "+f"(c[1]), "+f"(c[2]), "+f"(c[3])
                 : "r"(a[0]), "r"(a[1]), "r"(a[2]), "r"(a[3]), "r"(b[0]), "r"(b[1]));
}
__device__ __forceinline__ void split_bf16(float v, ush& h, ush& l) {
    __nv_bfloat16 hb = __float2bfloat16(v);
    float hf = __bfloat162float(hb);
    __nv_bfloat16 lb = __float2bfloat16(v - hf);
    h = __bfloat16_as_ushort(hb);
    l = __bfloat16_as_ushort(lb);
}
__device__ __forceinline__ float us2f(ush u) {
    return __bfloat162float(__ushort_as_bfloat16(u));
}

// ---------------- small kernels ----------------
__global__ void zerok(float* p, int n) {
    int i = blockIdx.x * 256 + threadIdx.x;
    if (i < n) p[i] = 0.f;
}
__global__ void copyk(const float* __restrict__ s, float* __restrict__ d, int n) {
    int i = blockIdx.x * 256 + threadIdx.x;
    if (i < n) d[i] = s[i];
}

// build X0 = [x | h] split, ld = F
__global__ void build_cat(ush* __restrict__ dh, ush* __restrict__ dl,
                          const float* __restrict__ xsrc, int xmode, int t,
                          const float* __restrict__ st, int Fi) {
    int F = Fi + UU;
    int idx = blockIdx.x * 256 + threadIdx.x;
    if (idx >= ROWS * F) return;
    int row = idx / F;
    int f = idx - row * F;
    int n = row >> 6, b = row & 63;
    float v;
    if (f < Fi) {
        if (xmode == 0)      v = xsrc[((long)b * TT + t) * 40000 + (long)n * 200 + f];
        else if (xmode == 1) v = xsrc[(long)b * 40000 + (long)n * 200 + f];
        else if (xmode == 2) v = 0.f;
        else                 v = xsrc[row * UU + f];
    } else {
        v = st[row * UU + (f - Fi)];
    }
    ush h, l;
    split_bf16(v, h, l);
    dh[idx] = h; dl[idx] = l;
}

// s2 prep: out = 2*S@S (200x200), FFMA one-time exact
#define DBK 8
__global__ __launch_bounds__(256) void s2_k(const float* __restrict__ S,
                                            float* __restrict__ out) {
    __shared__ float As[DBK][40];
    __shared__ float Bs[DBK][128];
    int tid = threadIdx.x;
    int tx = tid & 31, ty = tid >> 5;
    int n0 = blockIdx.x * 128;
    int m0 = blockIdx.y * 40;
    float acc[5][4];
#pragma unroll
    for (int i = 0; i < 5; i++)
#pragma unroll
        for (int j = 0; j < 4; j++) acc[i][j] = 0.f;
    for (int k0 = 0; k0 < 200; k0 += DBK) {
        As[tid & 7][tid >> 3] = S[(m0 + (tid >> 3)) * 200 + k0 + (tid & 7)];
        if (tid < 64) As[tid & 7][(256 + tid) >> 3] = S[(m0 + ((256 + tid) >> 3)) * 200 + k0 + (tid & 7)];
        float4 b4 = make_float4(0.f, 0.f, 0.f, 0.f);
        int gn = n0 + tx * 4;
        if (gn < 200) {
            const float* p = &S[(k0 + ty) * 200 + gn];
            b4.x = p[0]; b4.y = (gn + 1 < 200) ? p[1] : 0.f;
            b4.z = (gn + 2 < 200) ? p[2] : 0.f; b4.w = (gn + 3 < 200) ? p[3] : 0.f;
        }
        *reinterpret_cast<float4*>(&Bs[ty][tx * 4]) = b4;
        __syncthreads();
#pragma unroll
        for (int kk = 0; kk < DBK; kk++) {
            float a[5], b[4];
#pragma unroll
            for (int i = 0; i < 5; i++) a[i] = As[kk][ty * 5 + i];
#pragma unroll
            for (int j = 0; j < 4; j++) b[j] = Bs[kk][tx * 4 + j];
#pragma unroll
            for (int i = 0; i < 5; i++)
#pragma unroll
                for (int j = 0; j < 4; j++) acc[i][j] += a[i] * b[j];
        }
        __syncthreads();
    }
#pragma unroll
    for (int i = 0; i < 5; i++) {
        int gm = m0 + ty * 5 + i;
#pragma unroll
        for (int j = 0; j < 4; j++) {
            int gn = n0 + tx * 4 + j;
            if (gm < 200 && gn < 200) out[gm * 200 + gn] = 2.f * acc[i][j];
        }
    }
}

__global__ void ssplit(const float* __restrict__ SS,
                       ush* __restrict__ dh, ush* __restrict__ dl) {
    int idx = blockIdx.x * 256 + threadIdx.x;
    if (idx >= 512 * 208) return;
    int m = idx / 208, k = idx - m * 208;
    float v = (m < 400 && k < 200) ? SS[m * 200 + k] : 0.f;
    ush h, l;
    split_bf16(v, h, l);
    dh[idx] = h; dl[idx] = l;
}

// gate weight split transposed: dst[n][kb*Fw+f] = src[(f*3+kb)*ldsrc + n]
__global__ void wsplitT(const float* __restrict__ src, int ldsrc, int Fw,
                        int Kpad, int Nsrc,
                        ush* __restrict__ dh, ush* __restrict__ dl) {
    int idx = blockIdx.x * 256 + threadIdx.x;
    if (idx >= Nsrc * Kpad) return;
    int n = idx / Kpad;
    int r = idx - n * Kpad;
    float v = 0.f;
    if (r < 3 * Fw) {
        int kb = r / Fw, f = r - kb * Fw;
        v = src[((long)f * 3 + kb) * ldsrc + n];
    }
    ush h, l;
    split_bf16(v, h, l);
    dh[idx] = h; dl[idx] = l;
}
// cand combined: k<3Fi from x-rows, then 192 from h-rows
__global__ void wsplit_cand(const float* __restrict__ src, int Fi, int Kpad,
                            ush* __restrict__ dh, ush* __restrict__ dl) {
    int idx = blockIdx.x * 256 + threadIdx.x;
    if (idx >= 64 * Kpad) return;
    int n = idx / Kpad;
    int k = idx - n * Kpad;
    float v = 0.f;
    if (k < 3 * Fi) {
        int kb = k / Fi, f = k - kb * Fi;
        v = src[((long)f * 3 + kb) * 64 + n];
    } else if (k < 3 * Fi + 192) {
        int kp = k - 3 * Fi;
        int kb = kp >> 6, u = kp & 63;
        v = src[((long)(Fi + u) * 3 + kb) * 64 + n];
    }
    ush h, l;
    split_bf16(v, h, l);
    dh[idx] = h; dl[idx] = l;
}
__global__ void wsplit_proj(const float* __restrict__ src,
                            ush* __restrict__ dh, ush* __restrict__ dl) {
    int idx = blockIdx.x * 256 + threadIdx.x;
    if (idx >= 256 * 64) return;
    int n = idx >> 6, k = idx & 63;
    float v = (n < 200) ? src[k * 200 + n] : 0.f;
    ush h, l;
    split_bf16(v, h, l);
    dh[idx] = h; dl[idx] = l;
}

#define ALD 24
#define BLD 24

// ---------------- mma diffusion kernel (split storage) ----------------
__global__ __launch_bounds__(256) void diffmma(
    const ush* __restrict__ SSh, const ush* __restrict__ SSl,
    const ush* __restrict__ X0h, const ush* __restrict__ X0l, int ldx,
    ush* __restrict__ X1h, ush* __restrict__ X1l,
    ush* __restrict__ X2h, ush* __restrict__ X2l)
{
    __shared__ __align__(16) ush Ah[2][128][ALD], Al[2][128][ALD];
    __shared__ __align__(16) ush Bh[2][64][BLD], Bl[2][64][BLD];
    int tid = threadIdx.x, wid = tid >> 5, lane = tid & 31;
    int wm = wid >> 1, wn = wid & 1;
    int m0 = blockIdx.y * 128, n0 = blockIdx.x * 64;

    float acc[2][4][4];
#pragma unroll
    for (int i = 0; i < 2; i++)
#pragma unroll
        for (int j = 0; j < 4; j++)
#pragma unroll
            for (int q = 0; q < 4; q++) acc[i][j][q] = 0.f;

    uint32_t sAh = smem_u32(Ah), sAl = smem_u32(Al);
    uint32_t sBh = smem_u32(Bh), sBl = smem_u32(Bl);
    int lr = (lane & 7) + ((lane >> 3) & 1) * 8;
    int lc = (lane >> 4) * 8;
    int br7 = lane & 7, bsel = (lane >> 3) & 1;

    int ar = tid >> 1, ak8 = (tid & 1) * 8;
    int bk = tid >> 4, bn4 = (tid & 15) * 4;

    uint4 rah, ral; uint2 rbh2, rbl2;
    auto fetch = [&](int k0) {
        rah = *reinterpret_cast<const uint4*>(SSh + (long)(m0 + ar) * 208 + k0 + ak8);
        ral = *reinterpret_cast<const uint4*>(SSl + (long)(m0 + ar) * 208 + k0 + ak8);
        int k = k0 + bk;
        if (k < 200) {
            long off = (long)k * ldx + n0 + bn4;
            rbh2 = *reinterpret_cast<const uint2*>(X0h + off);
            rbl2 = *reinterpret_cast<const uint2*>(X0l + off);
        } else {
            rbh2 = make_uint2(0, 0); rbl2 = make_uint2(0, 0);
        }
    };
    auto store = [&](int buf) {
        *reinterpret_cast<uint4*>(&Ah[buf][ar][ak8]) = rah;
        *reinterpret_cast<uint4*>(&Al[buf][ar][ak8]) = ral;
        ush hs[4], ls[4];
        *reinterpret_cast<uint2*>(hs) = rbh2;
        *reinterpret_cast<uint2*>(ls) = rbl2;
#pragma unroll
        for (int j = 0; j < 4; j++) {
            Bh[buf][bn4 + j][bk] = hs[j];
            Bl[buf][bn4 + j][bk] = ls[j];
        }
    };

    fetch(0); store(0); __syncthreads();
    const int nk = 13;
    for (int kt = 0; kt < nk; kt++) {
        int cur = kt & 1;
        if (kt + 1 < nk) fetch((kt + 1) * 16);
        uint32_t ah[2][4], al[2][4], bh[4][2], bl[4][2];
#pragma unroll
        for (int mi = 0; mi < 2; mi++) {
            uint32_t off = (uint32_t)(((cur * 128 + wm * 32 + mi * 16 + lr) * ALD + lc) * 2);
            ldm_x4(sAh + off, ah[mi][0], ah[mi][1], ah[mi][2], ah[mi][3]);
            ldm_x4(sAl + off, al[mi][0], al[mi][1], al[mi][2], al[mi][3]);
        }
#pragma unroll
        for (int nf = 0; nf < 4; nf++) {
            uint32_t off = (uint32_t)(((cur * 64 + wn * 32 + nf * 8 + br7) * BLD + bsel * 8) * 2);
            ldm_x2(sBh + off, bh[nf][0], bh[nf][1]);
            ldm_x2(sBl + off, bl[nf][0], bl[nf][1]);
        }
#pragma unroll
        for (int mi = 0; mi < 2; mi++)
#pragma unroll
            for (int nf = 0; nf < 4; nf++) {
                mma16816(acc[mi][nf], ah[mi], bh[nf]);
                mma16816(acc[mi][nf], al[mi], bh[nf]);
                mma16816(acc[mi][nf], ah[mi], bl[nf]);
            }
        if (kt + 1 < nk) { store(cur ^ 1); __syncthreads(); }
    }

    int g = lane >> 2, tq = lane & 3;
#pragma unroll
    for (int mi = 0; mi < 2; mi++) {
#pragma unroll
        for (int nf = 0; nf < 4; nf++) {
            int cn = n0 + wn * 32 + nf * 8 + 2 * tq;
#pragma unroll
            for (int e = 0; e < 4; e++) {
                int gm = m0 + wm * 32 + mi * 16 + g + (e >> 1) * 8;
                int cc = cn + (e & 1);
                float v = acc[mi][nf][e];
                ush h, l;
                if (gm < 200) {
                    long p = (long)gm * ldx + cc;
                    split_bf16(v, h, l);
                    X1h[p] = h; X1l[p] = l;
                } else if (gm < 400) {
                    long p = (long)(gm - 200) * ldx + cc;
                    float x0 = us2f(X0h[p]) + us2f(X0l[p]);
                    split_bf16(v - x0, h, l);
                    X2h[p] = h; X2l[p] = l;
                }
            }
        }
    }
}

// ---------------- mma feature GEMM, two A-sources, fused epilogues ----------
// MODE: 2 gates, 3 cand+GRU (fused x+h), 4 projection
template<int MODE>
__device__ __forceinline__ void epi(float v, int gm, int cn,
    const float* bias, const float* H, const float* Uin,
    float* Of1, float* Of2, ush* Oh, ush* Ol, int t)
{
    if (MODE == 2) {
        float s = 1.f / (1.f + expf(-(v + bias[cn])));
        if (cn < UU) {
            ush h, l;
            split_bf16(s * H[gm * UU + cn], h, l);
            Oh[gm * UU + cn] = h; Ol[gm * UU + cn] = l;
        } else {
            Of1[gm * UU + cn - UU] = s;
        }
    } else if (MODE == 3) {
        float c = tanhf(v + bias[cn]);
        float u = Uin[gm * UU + cn];
        float hn = u * H[gm * UU + cn] + (1.f - u) * c;
        Of1[gm * UU + cn] = hn;
        if (Oh) {
            ush h, l;
            split_bf16(hn, h, l);
            Oh[gm * UU + cn] = h; Ol[gm * UU + cn] = l;
        }
    } else if (MODE == 4) {
        if (cn < 200) {
            float p = v + bias[cn];
            int b_ = gm & 63, n_ = gm >> 6;
            Of1[((long)b_ * TT + t) * 40000 + (long)n_ * 200 + cn] = p;
            Of2[(long)b_ * 40000 + (long)n_ * 200 + cn] = p;
        }
    }
}

template<int MODE>
__global__ __launch_bounds__(256) void featmma(
    const ush* __restrict__ A1h, const ush* __restrict__ A1l,
    int lda1, int Fb1, long ch1, int KA,
    const ush* __restrict__ A2h, const ush* __restrict__ A2l, long ch2,
    int K,
    const ush* __restrict__ Bwh, const ush* __restrict__ Bwl, int Kpad, int Nn,
    const float* __restrict__ bias, const float* __restrict__ H,
    const float* __restrict__ Uin,
    float* __restrict__ Of1, float* __restrict__ Of2,
    ush* __restrict__ Oh, ush* __restrict__ Ol, int t)
{
    __shared__ __align__(16) ush Ah[2][128][ALD], Al[2][128][ALD];
    __shared__ __align__(16) ush Bh[2][64][BLD], Bl[2][64][BLD];
    int tid = threadIdx.x, wid = tid >> 5, lane = tid & 31;
    int wm = wid >> 1, wn = wid & 1;
    int m0 = blockIdx.y * 128, n0 = blockIdx.x * 64;

    float acc[2][4][4];
#pragma unroll
    for (int i = 0; i < 2; i++)
#pragma unroll
        for (int j = 0; j < 4; j++)
#pragma unroll
            for (int q = 0; q < 4; q++) acc[i][j][q] = 0.f;

    uint32_t sAh = smem_u32(Ah), sAl = smem_u32(Al);
    uint32_t sBh = smem_u32(Bh), sBl = smem_u32(Bl);
    int lr = (lane & 7) + ((lane >> 3) & 1) * 8;
    int lc = (lane >> 4) * 8;
    int br7 = lane & 7, bsel = (lane >> 3) & 1;

    int ar = tid >> 1, ak8 = (tid & 1) * 8;
    int bn = tid >> 2, bk4 = (tid & 3) * 4;

    uint4 rah, ral; uint2 rbh, rbl;
    auto fetch = [&](int k0) {
        int k8 = k0 + ak8;
        if (k8 < K) {
            long off;
            if (k8 < KA) {
                int kb = k8 / Fb1, krel = k8 - kb * Fb1;
                off = (long)kb * ch1 + (long)(m0 + ar) * lda1 + krel;
                rah = *reinterpret_cast<const uint4*>(A1h + off);
                ral = *reinterpret_cast<const uint4*>(A1l + off);
            } else {
                int kp = k8 - KA;
                int kb = kp >> 6, krel = kp & 63;
                off = (long)kb * ch2 + (long)(m0 + ar) * 64 + krel;
                rah = *reinterpret_cast<const uint4*>(A2h + off);
                ral = *reinterpret_cast<const uint4*>(A2l + off);
            }
        } else {
            rah = make_uint4(0, 0, 0, 0);
            ral = make_uint4(0, 0, 0, 0);
        }
        long boff = (long)(n0 + bn) * Kpad + k0 + bk4;
        rbh = *reinterpret_cast<const uint2*>(Bwh + boff);
        rbl = *reinterpret_cast<const uint2*>(Bwl + boff);
    };
    auto store = [&](int buf) {
        *reinterpret_cast<uint4*>(&Ah[buf][ar][ak8]) = rah;
        *reinterpret_cast<uint4*>(&Al[buf][ar][ak8]) = ral;
        *reinterpret_cast<uint2*>(&Bh[buf][bn][bk4]) = rbh;
        *reinterpret_cast<uint2*>(&Bl[buf][bn][bk4]) = rbl;
    };

    int nk = (K + 15) / 16;
    fetch(0); store(0); __syncthreads();
    for (int kt = 0; kt < nk; kt++) {
        int cur = kt & 1;
        if (kt + 1 < nk) fetch((kt + 1) * 16);
        uint32_t ah[2][4], al[2][4], bh[4][2], bl[4][2];
#pragma unroll
        for (int mi = 0; mi < 2; mi++) {
            uint32_t off = (uint32_t)(((cur * 128 + wm * 32 + mi * 16 + lr) * ALD + lc) * 2);
            ldm_x4(sAh + off, ah[mi][0], ah[mi][1], ah[mi][2], ah[mi][3]);
            ldm_x4(sAl + off, al[mi][0], al[mi][1], al[mi][2], al[mi][3]);
        }
#pragma unroll
        for (int nf = 0; nf < 4; nf++) {
            uint32_t off = (uint32_t)(((cur * 64 + wn * 32 + nf * 8 + br7) * BLD + bsel * 8) * 2);
            ldm_x2(sBh + off, bh[nf][0], bh[nf][1]);
            ldm_x2(sBl + off, bl[nf][0], bl[nf][1]);
        }
#pragma unroll
        for (int mi = 0; mi < 2; mi++)
#pragma unroll
            for (int nf = 0; nf < 4; nf++) {
                mma16816(acc[mi][nf], ah[mi], bh[nf]);
                mma16816(acc[mi][nf], al[mi], bh[nf]);
                mma16816(acc[mi][nf], ah[mi], bl[nf]);
            }
        if (kt + 1 < nk) { store(cur ^ 1); __syncthreads(); }
    }

    int g = lane >> 2, tq = lane & 3;
#pragma unroll
    for (int mi = 0; mi < 2; mi++)
#pragma unroll
        for (int nf = 0; nf < 4; nf++) {
            int cn = n0 + wn * 32 + nf * 8 + 2 * tq;
#pragma unroll
            for (int e = 0; e < 4; e++) {
                int gm = m0 + wm * 32 + mi * 16 + g + (e >> 1) * 8;
                int cc = cn + (e & 1);
                if (cc < Nn)
                    epi<MODE>(acc[mi][nf][e], gm, cc, bias, H, Uin, Of1, Of2, Oh, Ol, t);
            }
        }
}

// ---------------- host orchestration ----------------
extern "C" void kernel_launch(void* const* d_in, const int* in_sizes, int n_in,
                              void* d_out, int out_size) {
    (void)in_sizes; (void)n_in; (void)out_size;
    const float* inputs  = (const float*)d_in[0];
    const float* Ssup    = (const float*)d_in[1];
    const float* enc_Wg0 = (const float*)d_in[2];
    const float* enc_bg0 = (const float*)d_in[3];
    const float* enc_Wc0 = (const float*)d_in[4];
    const float* enc_bc0 = (const float*)d_in[5];
    const float* enc_Wg  = (const float*)d_in[6];
    const float* enc_bg  = (const float*)d_in[7];
    const float* enc_Wc  = (const float*)d_in[8];
    const float* enc_bc  = (const float*)d_in[9];
    const float* dec_Wg0 = (const float*)d_in[10];
    const float* dec_bg0 = (const float*)d_in[11];
    const float* dec_Wc0 = (const float*)d_in[12];
    const float* dec_bc0 = (const float*)d_in[13];
    const float* dec_Wg  = (const float*)d_in[14];
    const float* dec_bg  = (const float*)d_in[15];
    const float* dec_Wc  = (const float*)d_in[16];
    const float* dec_bc  = (const float*)d_in[17];
    const float* proj_W  = (const float*)d_in[18];
    const float* proj_b  = (const float*)d_in[19];
    float* out = (float*)d_out;

    float *pU, *pH, *pPROJ, *pSS;
    cudaGetSymbolAddress((void**)&pU,    g_U);
    cudaGetSymbolAddress((void**)&pH,    g_H);
    cudaGetSymbolAddress((void**)&pPROJ, g_PROJ);
    cudaGetSymbolAddress((void**)&pSS,   g_SS);
    ush *pXh, *pXl, *pRHh, *pRHl, *ph3h, *ph3l, *pSSh, *pSSl, *pBph, *pBpl;
    cudaGetSymbolAddress((void**)&pXh,  g_Xh);
    cudaGetSymbolAddress((void**)&pXl,  g_Xl);
    cudaGetSymbolAddress((void**)&pRHh, g_RHh);
    cudaGetSymbolAddress((void**)&pRHl, g_RHl);
    cudaGetSymbolAddress((void**)&ph3h, g_h3h);
    cudaGetSymbolAddress((void**)&ph3l, g_h3l);
    cudaGetSymbolAddress((void**)&pSSh, g_SSh);
    cudaGetSymbolAddress((void**)&pSSl, g_SSl);
    cudaGetSymbolAddress((void**)&pBph, g_Bph);
    cudaGetSymbolAddress((void**)&pBpl, g_Bpl);
    ush *pBgh[2], *pBgl[2], *pBch[2], *pBcl[2];
    cudaGetSymbolAddress((void**)&pBgh[0], g_Bgh_e);
    cudaGetSymbolAddress((void**)&pBgl[0], g_Bgl_e);
    cudaGetSymbolAddress((void**)&pBgh[1], g_Bgh_d);
    cudaGetSymbolAddress((void**)&pBgl[1], g_Bgl_d);
    cudaGetSymbolAddress((void**)&pBch[0], g_Bch_e);
    cudaGetSymbolAddress((void**)&pBcl[0], g_Bcl_e);
    cudaGetSymbolAddress((void**)&pBch[1], g_Bch_d);
    cudaGetSymbolAddress((void**)&pBcl[1], g_Bcl_d);

    // ---- prep ----
    copyk<<<(40000 + 255) / 256, 256>>>(Ssup, pSS, 40000);
    s2_k<<<dim3(2, 5), 256>>>(Ssup, pSS + 40000);
    ssplit<<<(512 * 208 + 255) / 256, 256>>>(pSS, pSSh, pSSl);

    const float* Wg0s[2] = {enc_Wg0, dec_Wg0};
    const float* Wgs[2]  = {enc_Wg,  dec_Wg};
    const float* Wc0s[2] = {enc_Wc0, dec_Wc0};
    const float* Wcs[2]  = {enc_Wc,  dec_Wc};
    for (int s = 0; s < 2; s++) {
        wsplitT<<<(128 * 800 + 255) / 256, 256>>>(Wg0s[s], 128, 264, 800, 128,
                                                  pBgh[s], pBgl[s]);
        wsplit_cand<<<(64 * 800 + 255) / 256, 256>>>(Wc0s[s], 200, 800,
                                                     pBch[s], pBcl[s]);
        for (int i = 0; i < 3; i++) {
            wsplitT<<<(128 * 384 + 255) / 256, 256>>>(Wgs[s] + (long)i * 384 * 128, 128,
                128, 384, 128,
                pBgh[s] + 128 * 800 + (long)i * 128 * 384,
                pBgl[s] + 128 * 800 + (long)i * 128 * 384);
            wsplit_cand<<<(64 * 384 + 255) / 256, 256>>>(Wcs[s] + (long)i * 384 * 64, 64, 384,
                pBch[s] + 64 * 800 + (long)i * 64 * 384,
                pBcl[s] + 64 * 800 + (long)i * 64 * 384);
        }
    }
    wsplit_proj<<<64, 256>>>(proj_W, pBph, pBpl);
    zerok<<<(LL * ROWS * UU) / 256, 256>>>(pH, LL * ROWS * UU);

    ush* RHD1h = pRHh + RHCH; ush* RHD1l = pRHl + RHCH;
    ush* RHD2h = pRHh + 2 * RHCH; ush* RHD2l = pRHl + 2 * RHCH;

    // ---- sequence loop ----
    for (int tg = 0; tg < 2 * TT; tg++) {
        bool enc = (tg < TT);
        int side = enc ? 0 : 1;
        int t = enc ? tg : (tg - TT);

        for (int l = 0; l < LL; l++) {
            int Fi = (l == 0) ? 200 : 64;
            int F = Fi + UU;
            int BF = BB * F;
            float* hl = pH + (long)l * ROWS * UU;

            const ush* Bgh = pBgh[side] + ((l == 0) ? 0 : 128 * 800 + (long)(l - 1) * 128 * 384);
            const ush* Bgl = pBgl[side] + ((l == 0) ? 0 : 128 * 800 + (long)(l - 1) * 128 * 384);
            int Kpg = (l == 0) ? 800 : 384;
            const ush* Bch = pBch[side] + ((l == 0) ? 0 : 64 * 800 + (long)(l - 1) * 64 * 384);
            const ush* Bcl = pBcl[side] + ((l == 0) ? 0 : 64 * 800 + (long)(l - 1) * 64 * 384);
            const float* bg = enc ? ((l == 0) ? enc_bg0 : enc_bg + (l - 1) * 128)
                                  : ((l == 0) ? dec_bg0 : dec_bg + (l - 1) * 128);
            const float* bc = enc ? ((l == 0) ? enc_bc0 : enc_bc + (l - 1) * 64)
                                  : ((l == 0) ? dec_bc0 : dec_bc + (l - 1) * 64);

            int xmode;
            const float* xsrc;
            if (l > 0)       { xmode = 3; xsrc = pH + (long)(l - 1) * ROWS * UU; }
            else if (enc)    { xmode = 0; xsrc = inputs; }
            else if (t == 0) { xmode = 2; xsrc = pPROJ; }
            else             { xmode = 1; xsrc = pPROJ; }

            build_cat<<<(ROWS * F) / 256, 256>>>(pXh, pXl, xsrc, xmode, t, hl, Fi);
            diffmma<<<dim3(BF / 64, 4), 256>>>(pSSh, pSSl, pXh, pXl, BF,
                pXh + CHUNK, pXl + CHUNK, pXh + 2 * CHUNK, pXl + 2 * CHUNK);
            // gates
            featmma<2><<<dim3(2, 100), 256>>>(pXh, pXl, F, F, (long)CHUNK, 3 * F,
                nullptr, nullptr, 0, 3 * F, Bgh, Bgl, Kpg, 128,
                bg, hl, nullptr, pU, nullptr, pRHh, pRHl, 0);
            // rh diffusion
            diffmma<<<dim3(64, 4), 256>>>(pSSh, pSSl, pRHh, pRHl, 4096,
                RHD1h, RHD1l, RHD2h, RHD2l);
            // candidate (fused x + h parts) + GRU update
            featmma<3><<<dim3(1, 100), 256>>>(pXh, pXl, F, Fi, (long)CHUNK, 3 * Fi,
                pRHh, pRHl, (long)RHCH, 3 * Fi + 192, Bch, Bcl, Kpg, 64,
                bc, hl, pU, hl, nullptr,
                (l == 3) ? ph3h : nullptr, (l == 3) ? ph3l : nullptr, 0);
        }

        if (!enc) {
            featmma<4><<<dim3(4, 100), 256>>>(ph3h, ph3l, 64, 64, 0, 64,
                nullptr, nullptr, 0, 64, pBph, pBpl, 64, 200,
                proj_b, nullptr, nullptr, out, pPROJ, nullptr, nullptr, t);
        }
    }
}